// round 8
// baseline (speedup 1.0000x reference)
#include <cuda_runtime.h>
#include <cuda_fp16.h>
#include <cstdint>

#define NGRAPH 8192
#define NNODE (NGRAPH * 32)
#define NEDGE 524288

typedef __half h16;

// ================= static device scratch =================
__device__ __align__(16) int  g_adj[NGRAPH * 1024];
__device__ __align__(16) h16  g_Wio[256 * 128];
__device__ __align__(16) h16  g_Wg[512 * 384];
__device__ __align__(16) h16  g_Wu[128 * 128];
__device__ __align__(16) h16  g_Wv[128 * 128];
__device__ __align__(16) float g_biasY[256];
__device__ __align__(16) float g_biasG[512];

// ================= smem map =================
// OFF_A: 6 tiles x 16KB h16 [128 rows][64 cols] swizzled.
//   tiles 0-3: Agg cols 0..255 (later tiles 0,1 hold hn cols 0..127)
//   tiles 4,5: feat cols 0..127
// OFF_B: 96KB streaming region (feat-f32 / Wio / sC / gates Wg stages / sG / Wu+Wv)
// OFF_ADJ: adjacency floats (inside upper B region; dead before gates)
// OFF_MISC: small f32 arrays
#define OFF_A    0
#define OFF_B    98304
#define OFF_ADJ  (98304 + 67584)
#define OFF_MISC 196608
#define SMEM_TOTAL (196608 + 11264)

// ================= helpers =================
__device__ __forceinline__ uint32_t smem_to_u32(const void* p) {
  uint32_t a;
  asm("{ .reg .u64 tmp; cvta.to.shared.u64 tmp, %1; cvt.u32.u64 %0, tmp; }"
      : "=r"(a) : "l"(p));
  return a;
}
#define SWZ(off) ((off) ^ (((off) >> 3) & 0x70))

__device__ __forceinline__ void cp16(uint32_t dst, const void* src) {
  asm volatile("cp.async.cg.shared.global [%0], [%1], 16;" ::"r"(dst), "l"(src));
}
#define CP_COMMIT() asm volatile("cp.async.commit_group;" ::: "memory")
#define CP_WAIT(n) asm volatile("cp.async.wait_group %0;" ::"n"(n) : "memory")

__device__ __forceinline__ void ldsm_x4(uint32_t addr, uint32_t* r) {
  asm volatile("ldmatrix.sync.aligned.m8n8.x4.shared.b16 {%0,%1,%2,%3}, [%4];"
               : "=r"(r[0]), "=r"(r[1]), "=r"(r[2]), "=r"(r[3]) : "r"(addr));
}
__device__ __forceinline__ void mma16816(float* d, const uint32_t* a,
                                         const uint32_t* b) {
  asm volatile(
      "mma.sync.aligned.m16n8k16.row.col.f32.f16.f16.f32 "
      "{%0,%1,%2,%3}, {%4,%5,%6,%7}, {%8,%9}, {%0,%1,%2,%3};"
      : "+f"(d[0]), "+f"(d[1]), "+f"(d[2]), "+f"(d[3])
      : "r"(a[0]), "r"(a[1]), "r"(a[2]), "r"(a[3]), "r"(b[0]), "r"(b[1]));
}

__device__ __forceinline__ float sigf(float x) { return 1.f / (1.f + __expf(-x)); }
__device__ __forceinline__ float tanh_fast(float x) {
  float e2x = __expf(2.f * x);
  return 1.f - 2.f / (e2x + 1.f);
}
__device__ __forceinline__ float h2f(h16 v) { return __half2float(v); }
__device__ __forceinline__ uint32_t pack2h(float a, float b) {
  __half2 h = __floats2half2_rn(a, b);
  return *(uint32_t*)&h;
}

// ================= adjacency =================
__global__ void k_zero_adj() {
  int i = blockIdx.x * blockDim.x + threadIdx.x;
  int stride = gridDim.x * blockDim.x;
  int4* p = (int4*)g_adj;
  const int n4 = NGRAPH * 1024 / 4;
  int4 z = make_int4(0, 0, 0, 0);
  for (; i < n4; i += stride) p[i] = z;
}
__global__ void k_build_adj(const int* __restrict__ src, const int* __restrict__ dst) {
  int e = blockIdx.x * blockDim.x + threadIdx.x;
  if (e >= NEDGE) return;
  int d = dst[e];
  int s = src[e];
  atomicAdd(&g_adj[((d >> 5) << 10) + ((d & 31) << 5) + (s & 31)], 1);
}

// ================= weight pack =================
__global__ void k_pack(const float* __restrict__ W_in, const float* __restrict__ W_og,
                       const float* __restrict__ W_ih, const float* __restrict__ W_hh,
                       const float* __restrict__ W_u, const float* __restrict__ W_v,
                       const float* __restrict__ b_in, const float* __restrict__ b_og,
                       const float* __restrict__ b_ih, const float* __restrict__ b_hh) {
  int i0 = blockIdx.x * 256 + threadIdx.x;
  int stride = gridDim.x * 256;
  for (int i = i0; i < 256 * 128; i += stride) {
    int r = i >> 7, c = i & 127;
    float v = (r < 128) ? W_in[r * 128 + c] : W_og[(r - 128) * 128 + c];
    g_Wio[i] = __float2half_rn(v);
  }
  for (int i = i0; i < 512 * 384; i += stride) {
    int r = i / 384, c = i % 384;
    int blk = r >> 7, rr = r & 127;
    float v;
    if (blk == 0)      v = (c < 256) ? W_ih[rr * 256 + c] : W_hh[rr * 128 + (c - 256)];
    else if (blk == 1) v = (c < 256) ? W_ih[(128 + rr) * 256 + c] : W_hh[(128 + rr) * 128 + (c - 256)];
    else if (blk == 2) v = (c < 256) ? W_ih[(256 + rr) * 256 + c] : 0.f;
    else               v = (c < 256) ? 0.f : W_hh[(256 + rr) * 128 + (c - 256)];
    g_Wg[i] = __float2half_rn(v);
  }
  for (int i = i0; i < 128 * 128; i += stride) {
    g_Wu[i] = __float2half_rn(W_u[i]);
    g_Wv[i] = __float2half_rn(W_v[i]);
  }
  for (int i = i0; i < 256; i += stride)
    g_biasY[i] = (i < 128) ? b_in[i] : b_og[i - 128];
  for (int i = i0; i < 512; i += stride) {
    float v;
    if (i < 256)      v = b_ih[i] + b_hh[i];
    else if (i < 384) v = b_ih[i];
    else              v = b_hh[i - 128];
    g_biasG[i] = v;
  }
}

// ================= the fused layer kernel =================
__global__ void __launch_bounds__(256, 1) k_fused(
    const float* __restrict__ feat, const float* __restrict__ cnt,
    const float* __restrict__ b_v, const float* __restrict__ we,
    float* __restrict__ out) {
  extern __shared__ __align__(1024) char smem[];
  const uint32_t sb = smem_to_u32(smem);
  const int tid = threadIdx.x;
  const int lid = tid & 31, wid = tid >> 5;
  const int m0 = blockIdx.x * 128;
  const int g0 = m0 >> 5;

  float* MISC = (float*)(smem + OFF_MISC);
  float* mBiasY = MISC;
  float* mBiasG = MISC + 256;
  float* mBv    = MISC + 768;
  float* mRin   = MISC + 896;
  float* mRout  = MISC + 1024;
  float* mLast  = MISC + 1152;   // [4][128] f32
  float* mFV    = MISC + 1664;   // [4][128]
  float* mPart  = MISC + 2176;   // [2][128]
  float* mAl    = MISC + 2432;   // [128]
  float* mWe    = MISC + 2560;
  float* mCnt   = MISC + 2688;
  float* sAdj   = (float*)(smem + OFF_ADJ);

  // ---------- phase 0: feat (cp.async) + adj + biases ----------
#pragma unroll
  for (int i = 0; i < 16; i++) {
    int u = tid + 256 * i;
    cp16(sb + OFF_B + u * 16, feat + (size_t)m0 * 128 + u * 4);
  }
  CP_COMMIT();
#pragma unroll
  for (int i = 0; i < 16; i++) {
    int u = tid + 256 * i;
    int gl = u >> 10, rem = u & 1023;
    sAdj[gl * 1056 + (rem >> 5) * 33 + (rem & 31)] =
        (float)g_adj[((size_t)(g0 + gl) << 10) + rem];
  }
  if (tid < 128) {
    mBiasY[tid] = g_biasY[tid];
    mBiasY[128 + tid] = g_biasY[128 + tid];
    mBv[tid] = b_v[tid];
    mWe[tid] = we[tid];
    mCnt[tid] = cnt[m0 + tid];
  } else {
    int t = tid - 128;
    mBiasG[t] = g_biasG[t];
    mBiasG[128 + t] = g_biasG[128 + t];
    mBiasG[256 + t] = g_biasG[256 + t];
    mBiasG[384 + t] = g_biasG[384 + t];
  }
  __syncthreads();
  {  // degrees
    int gl = (tid & 127) >> 5, n = tid & 31;
    float s = 0.f;
    if (tid < 128) {
#pragma unroll
      for (int k = 0; k < 32; k++) s += sAdj[gl * 1056 + n * 33 + k];
      mRin[tid] = 1.f / fmaxf(s, 1.f);
    } else {
#pragma unroll
      for (int k = 0; k < 32; k++) s += sAdj[gl * 1056 + k * 33 + n];
      mRout[tid - 128] = 1.f / fmaxf(s, 1.f);
    }
  }
  CP_WAIT(0);
  __syncthreads();
  {  // convert feat f32 -> h16 tiles 4,5
    const float2* f2p = (const float2*)(smem + OFF_B);
#pragma unroll
    for (int i = 0; i < 32; i++) {
      int e = tid + 256 * i;
      int row = e >> 6, cp = e & 63;
      float2 v = f2p[e];
      int tile = 4 + (cp >> 5);
      *(uint32_t*)(smem + OFF_A + tile * 16384 + SWZ(row * 128 + (cp & 31) * 4)) =
          pack2h(v.x, v.y);
    }
  }
  __syncthreads();
  // load Wio (4 swizzled tiles) into sB
#pragma unroll
  for (int i = 0; i < 16; i++) {
    int u = tid + 256 * i;
    int bt = u >> 10, rem = u & 1023;
    int r = rem >> 3, seg = rem & 7;
    int nb = bt >> 1, ck = bt & 1;
    cp16(sb + OFF_B + bt * 16384 + SWZ(r * 128 + seg * 16),
         g_Wio + (size_t)(nb * 128 + r) * 128 + ck * 64 + seg * 8);
  }
  CP_COMMIT();
  CP_WAIT(0);
  __syncthreads();

  // ---------- phase 1: Y GEMM (128x256, K=128) + aggregation ----------
  {
    const int wm0 = (wid & 1) * 64, wn0 = (wid >> 1) * 64;
    const int j = lid >> 3, rr = lid & 7;
    float acc[4][8][4];
#pragma unroll
    for (int mi = 0; mi < 4; mi++)
#pragma unroll
      for (int ni = 0; ni < 8; ni++)
#pragma unroll
        for (int q = 0; q < 4; q++) acc[mi][ni][q] = 0.f;
#pragma unroll
    for (int ch = 0; ch < 2; ch++) {
      uint32_t abase = sb + OFF_A + (4 + ch) * 16384;
      uint32_t bbase = sb + OFF_B + ((wn0 >> 7) * 2 + ch) * 16384;
#pragma unroll
      for (int kk = 0; kk < 4; kk++) {
        uint32_t ah[4][4], bh[8][2];
#pragma unroll
        for (int mi = 0; mi < 4; mi++) {
          int row = wm0 + mi * 16 + (j & 1) * 8 + rr;
          int kb = kk * 32 + (j >> 1) * 16;
          ldsm_x4(abase + SWZ(row * 128 + kb), ah[mi]);
        }
#pragma unroll
        for (int p = 0; p < 4; p++) {
          int n = (wn0 & 127) + p * 16 + (j >> 1) * 8 + rr;
          int kb = kk * 32 + (j & 1) * 16;
          uint32_t t[4];
          ldsm_x4(bbase + SWZ(n * 128 + kb), t);
          bh[2 * p][0] = t[0]; bh[2 * p][1] = t[1];
          bh[2 * p + 1][0] = t[2]; bh[2 * p + 1][1] = t[3];
        }
#pragma unroll
        for (int mi = 0; mi < 4; mi++)
#pragma unroll
          for (int ni = 0; ni < 8; ni++)
            mma16816(acc[mi][ni], ah[mi], bh[ni]);
      }
    }
    __syncthreads();
    // epilogue: two N-halves, staged through sC + per-graph aggregation
    float* sC = (float*)(smem + OFF_B);
    const int gp = lid >> 2, tg = lid & 3;
#pragma unroll
    for (int s = 0; s < 2; s++) {
      if ((wid >> 2) == s) {
#pragma unroll
        for (int mi = 0; mi < 4; mi++)
#pragma unroll
          for (int ni = 0; ni < 8; ni++) {
            int r = wm0 + mi * 16 + gp;
            int c = (wn0 & 127) + ni * 8 + tg * 2;
            float b0 = mBiasY[s * 128 + c], b1 = mBiasY[s * 128 + c + 1];
            sC[r * 132 + c] = acc[mi][ni][0] + b0;
            sC[r * 132 + c + 1] = acc[mi][ni][1] + b1;
            sC[(r + 8) * 132 + c] = acc[mi][ni][2] + b0;
            sC[(r + 8) * 132 + c + 1] = acc[mi][ni][3] + b1;
          }
      }
      __syncthreads();
      {
        int gl = tid >> 6, jj = tid & 63;
        float a0[32], a1[32];
#pragma unroll
        for (int n = 0; n < 32; n++) { a0[n] = 0.f; a1[n] = 0.f; }
        for (int k = 0; k < 32; k++) {
          float c0 = sC[(gl * 32 + k) * 132 + jj];
          float c1 = sC[(gl * 32 + k) * 132 + jj + 64];
#pragma unroll
          for (int n = 0; n < 32; n++) {
            float w = (s == 0) ? sAdj[gl * 1056 + n * 33 + k]
                               : sAdj[gl * 1056 + k * 33 + n];
            a0[n] += w * c0;
            a1[n] += w * c1;
          }
        }
        const float* rdg = (s == 0) ? mRin : mRout;
#pragma unroll
        for (int n = 0; n < 32; n++) {
          float rd = rdg[gl * 32 + n];
          int row = gl * 32 + n;
          *(h16*)(smem + OFF_A + (s * 2) * 16384 + SWZ(row * 128 + jj * 2)) =
              __float2half_rn(a0[n] * rd);
          *(h16*)(smem + OFF_A + (s * 2 + 1) * 16384 + SWZ(row * 128 + jj * 2)) =
              __float2half_rn(a1[n] * rd);
        }
      }
      __syncthreads();
    }
  }

  // ---------- phase 2: gates GEMM + GRU (two 64-row halves) ----------
  {
    const int gate = wid >> 1;
    const int wm0g = (wid & 1) * 32;
    const int j = lid >> 3, rr = lid & 7;
    const int gp = lid >> 2, tg = lid & 3;

    auto issueWg = [&](int ch) {
      uint32_t base = sb + OFF_B + (ch & 1) * 49152;
#pragma unroll
      for (int slot = 0; slot < 3; slot++) {
        int bg = (slot < 2) ? slot : (ch >= 4 ? 3 : 2);
#pragma unroll
        for (int i = 0; i < 4; i++) {
          int u = tid + 256 * i;
          int r = u >> 3, seg = u & 7;
          cp16(base + slot * 16384 + SWZ(r * 128 + seg * 16),
               g_Wg + (size_t)(bg * 128 + r) * 384 + ch * 64 + seg * 8);
        }
      }
      CP_COMMIT();
    };

    for (int half = 0; half < 2; half++) {
      float acc[2][16][4];
#pragma unroll
      for (int mi = 0; mi < 2; mi++)
#pragma unroll
        for (int ni = 0; ni < 16; ni++)
#pragma unroll
          for (int q = 0; q < 4; q++) acc[mi][ni][q] = 0.f;

      issueWg(0);
      issueWg(1);
      for (int ch = 0; ch < 6; ch++) {
        if (ch < 5) CP_WAIT(1); else CP_WAIT(0);
        __syncthreads();
        bool active = (gate == 2) ? (ch < 4) : (gate == 3) ? (ch >= 4) : true;
        if (active) {
          uint32_t stg = sb + OFF_B + (ch & 1) * 49152;
          uint32_t bbase = stg + ((gate < 2) ? gate : 2) * 16384;
          uint32_t abase = sb + OFF_A + ch * 16384;
#pragma unroll
          for (int kk = 0; kk < 4; kk++) {
            uint32_t ah[2][4], bh[16][2];
#pragma unroll
            for (int mi = 0; mi < 2; mi++) {
              int row = half * 64 + wm0g + mi * 16 + (j & 1) * 8 + rr;
              int kb = kk * 32 + (j >> 1) * 16;
              ldsm_x4(abase + SWZ(row * 128 + kb), ah[mi]);
            }
#pragma unroll
            for (int p = 0; p < 8; p++) {
              int n = p * 16 + (j >> 1) * 8 + rr;
              int kb = kk * 32 + (j & 1) * 16;
              uint32_t t[4];
              ldsm_x4(bbase + SWZ(n * 128 + kb), t);
              bh[2 * p][0] = t[0]; bh[2 * p][1] = t[1];
              bh[2 * p + 1][0] = t[2]; bh[2 * p + 1][1] = t[3];
            }
#pragma unroll
            for (int mi = 0; mi < 2; mi++)
#pragma unroll
              for (int ni = 0; ni < 16; ni++)
                mma16816(acc[mi][ni], ah[mi], bh[ni]);
          }
        }
        __syncthreads();
        if (ch < 4) issueWg(ch + 2);
      }

      // gate exchange: warps 0-5 (r,z,i) dump raw fragments to sB
      if (gate < 3) {
        float4* dst = (float4*)((float*)(smem + OFF_B) +
                                ((gate * 2 + (wid & 1)) * 32 + lid) * 128);
#pragma unroll
        for (int mi = 0; mi < 2; mi++)
#pragma unroll
          for (int ni = 0; ni < 16; ni++)
            dst[mi * 16 + ni] = make_float4(acc[mi][ni][0], acc[mi][ni][1],
                                            acc[mi][ni][2], acc[mi][ni][3]);
      }
      __syncthreads();
      // warps 6,7 hold accH: compute GRU
      if (gate == 3) {
        const int w1 = wid & 1;
        const float* rB = (float*)(smem + OFF_B) + ((0 + w1) * 32 + lid) * 128;
        const float* zB = rB + 2 * 32 * 128;
        const float* iB = rB + 4 * 32 * 128;
#pragma unroll
        for (int mi = 0; mi < 2; mi++)
#pragma unroll
          for (int ni = 0; ni < 16; ni++) {
            int idx = (mi * 16 + ni) * 4;
            int c0 = ni * 8 + tg * 2;
#pragma unroll
            for (int qp = 0; qp < 4; qp += 2) {
              int row = wm0g + mi * 16 + gp + (qp ? 8 : 0);
              int rowfull = half * 64 + row;
              // feat pair from tiles 4,5
              uint32_t fh = *(uint32_t*)(smem + OFF_A + (4 + (c0 >> 6)) * 16384 +
                                         SWZ(rowfull * 128 + (c0 & 63) * 2));
              float2 fv = __half22float2(*(__half2*)&fh);
              float hn01[2];
#pragma unroll
              for (int c = 0; c < 2; c++) {
                int col = c0 + c;
                float r_ = sigf(rB[idx + qp + c] + mBiasG[col]);
                float z_ = sigf(zB[idx + qp + c] + mBiasG[128 + col]);
                float hs = acc[mi][ni][qp + c] + mBiasG[384 + col];
                float ng = tanh_fast(iB[idx + qp + c] + mBiasG[256 + col] + r_ * hs);
                float f = (c == 0) ? fv.x : fv.y;
                hn01[c] = (1.f - z_) * ng + z_ * f;
              }
              *(uint32_t*)(smem + OFF_A + (c0 >> 6) * 16384 +
                           SWZ(rowfull * 128 + (c0 & 63) * 2)) =
                  pack2h(hn01[0], hn01[1]);
              if ((rowfull & 31) == 31) {
                mLast[(rowfull >> 5) * 128 + c0] = hn01[0];
                mLast[(rowfull >> 5) * 128 + c0 + 1] = hn01[1];
              }
            }
          }
      }
      __syncthreads();
    }
  }

  // ---------- phase 3: FV + U GEMM + attention + output ----------
  {
    // load Wu (2 swizzled tiles) + Wv (linear) into sB
#pragma unroll
    for (int i = 0; i < 8; i++) {
      int u = tid + 256 * i;
      int ck = u >> 10, rem = u & 1023, r = rem >> 3, seg = rem & 7;
      cp16(sb + OFF_B + ck * 16384 + SWZ(r * 128 + seg * 16),
           g_Wu + (size_t)r * 128 + ck * 64 + seg * 8);
    }
#pragma unroll
    for (int i = 0; i < 8; i++) {
      int u = tid + 256 * i;
      cp16(sb + OFF_B + 32768 + u * 16, g_Wv + u * 8);
    }
    CP_COMMIT();
    CP_WAIT(0);
    __syncthreads();

    // FV[gl][j] = sLast[gl] . Wv[j] + bv[j]   (f32 x fp16)
#pragma unroll
    for (int v = 0; v < 2; v++) {
      int e = tid + v * 256;
      int gl = e >> 7, jx = e & 127;
      const __half2* wv = (const __half2*)(smem + OFF_B + 32768 + jx * 256);
      const float* hl = mLast + gl * 128;
      float s = 0.f;
#pragma unroll 16
      for (int k2 = 0; k2 < 64; k2++) {
        float2 w = __half22float2(wv[k2]);
        s += hl[2 * k2] * w.x + hl[2 * k2 + 1] * w.y;
      }
      mFV[e] = s + mBv[jx];
    }
    __syncthreads();

    // U GEMM: hn (tiles 0,1) @ Wu^T ; warp tile 32x64
    const int wm0u = (wid & 3) * 32, wn0u = (wid >> 2) * 64;
    const int j = lid >> 3, rr = lid & 7;
    float acc[2][8][4];
#pragma unroll
    for (int mi = 0; mi < 2; mi++)
#pragma unroll
      for (int ni = 0; ni < 8; ni++)
#pragma unroll
        for (int q = 0; q < 4; q++) acc[mi][ni][q] = 0.f;
#pragma unroll
    for (int ch = 0; ch < 2; ch++) {
      uint32_t abase = sb + OFF_A + ch * 16384;
      uint32_t bbase = sb + OFF_B + ch * 16384;
#pragma unroll
      for (int kk = 0; kk < 4; kk++) {
        uint32_t ah[2][4], bh[8][2];
#pragma unroll
        for (int mi = 0; mi < 2; mi++) {
          int row = wm0u + mi * 16 + (j & 1) * 8 + rr;
          int kb = kk * 32 + (j >> 1) * 16;
          ldsm_x4(abase + SWZ(row * 128 + kb), ah[mi]);
        }
#pragma unroll
        for (int p = 0; p < 4; p++) {
          int n = wn0u + p * 16 + (j >> 1) * 8 + rr;
          int kb = kk * 32 + (j & 1) * 16;
          uint32_t t[4];
          ldsm_x4(bbase + SWZ(n * 128 + kb), t);
          bh[2 * p][0] = t[0]; bh[2 * p][1] = t[1];
          bh[2 * p + 1][0] = t[2]; bh[2 * p + 1][1] = t[3];
        }
#pragma unroll
        for (int mi = 0; mi < 2; mi++)
#pragma unroll
          for (int ni = 0; ni < 8; ni++)
            mma16816(acc[mi][ni], ah[mi], bh[ni]);
      }
    }
    // attention partials
    const int gp = lid >> 2, tg = lid & 3;
#pragma unroll
    for (int mi = 0; mi < 2; mi++) {
      int base = wm0u + mi * 16;
      int gl = base >> 5;
      float p0 = 0.f, p1 = 0.f;
#pragma unroll
      for (int ni = 0; ni < 8; ni++) {
        int jx = wn0u + ni * 8 + tg * 2;
        float fv0 = mFV[gl * 128 + jx], fv1 = mFV[gl * 128 + jx + 1];
        float w0 = mWe[jx], w1 = mWe[jx + 1];
        p0 += w0 * sigf(acc[mi][ni][0] + fv0) + w1 * sigf(acc[mi][ni][1] + fv1);
        p1 += w0 * sigf(acc[mi][ni][2] + fv0) + w1 * sigf(acc[mi][ni][3] + fv1);
      }
      p0 += __shfl_xor_sync(0xffffffffu, p0, 1);
      p0 += __shfl_xor_sync(0xffffffffu, p0, 2);
      p1 += __shfl_xor_sync(0xffffffffu, p1, 1);
      p1 += __shfl_xor_sync(0xffffffffu, p1, 2);
      if (tg == 0) {
        mPart[(wn0u >> 6) * 128 + base + gp] = p0;
        mPart[(wn0u >> 6) * 128 + base + gp + 8] = p1;
      }
    }
    __syncthreads();
    if (tid < 128) mAl[tid] = (mPart[tid] + mPart[128 + tid]) * mCnt[tid];
    __syncthreads();

    // output: ct_g from smem hn, ct_l from f32 last rows
#pragma unroll
    for (int v = 0; v < 2; v++) {
      int idx = tid + v * 256;
      int gl = idx >> 7, jx = idx & 127;
      float s = 0.f;
#pragma unroll
      for (int n = 0; n < 32; n++) {
        float hn = h2f(*(h16*)(smem + OFF_A + (jx >> 6) * 16384 +
                               SWZ((gl * 32 + n) * 128 + (jx & 63) * 2)));
        s += hn * mAl[gl * 32 + n];
      }
      out[(size_t)(g0 + gl) * 256 + jx] = s;
      out[(size_t)(g0 + gl) * 256 + 128 + jx] = mLast[gl * 128 + jx];
    }
  }
}

// ================= host =================
extern "C" void kernel_launch(void* const* d_in, const int* in_sizes, int n_in,
                              void* d_out, int out_size) {
  const float* feat = (const float*)d_in[0];
  const float* cnt  = (const float*)d_in[1];
  const float* W_in = (const float*)d_in[2];
  const float* b_in = (const float*)d_in[3];
  const float* W_og = (const float*)d_in[4];
  const float* b_og = (const float*)d_in[5];
  const float* W_ih = (const float*)d_in[6];
  const float* b_ih = (const float*)d_in[7];
  const float* W_hh = (const float*)d_in[8];
  const float* b_hh = (const float*)d_in[9];
  const float* W_u  = (const float*)d_in[10];
  const float* W_v  = (const float*)d_in[11];
  const float* b_v  = (const float*)d_in[12];
  const float* w_e  = (const float*)d_in[13];
  const int*   src  = (const int*)d_in[14];
  const int*   dst  = (const int*)d_in[15];
  float* out = (float*)d_out;

  static bool attr_done = false;
  if (!attr_done) {
    cudaFuncSetAttribute(k_fused, cudaFuncAttributeMaxDynamicSharedMemorySize,
                         SMEM_TOTAL);
    attr_done = true;
  }

  k_zero_adj<<<512, 256>>>();
  k_build_adj<<<NEDGE / 256, 256>>>(src, dst);
  k_pack<<<256, 256>>>(W_in, W_og, W_ih, W_hh, W_u, W_v, b_in, b_og, b_ih, b_hh);
  k_fused<<<NNODE / 128, 256, SMEM_TOTAL>>>(feat, cnt, b_v, w_e, out);
}

// round 9
// speedup vs baseline: 1.2851x; 1.2851x over previous
#include <cuda_runtime.h>
#include <cuda_fp16.h>
#include <cstdint>

#define NGRAPH 8192
#define NNODE (NGRAPH * 32)
#define NEDGE 524288

typedef __half h16;

// ================= static device scratch =================
__device__ __align__(16) int  g_adj[NGRAPH * 1024];
__device__ __align__(16) h16  g_featH[(size_t)NNODE * 128];
__device__ __align__(16) h16  g_AggH[(size_t)NNODE * 256];
__device__ __align__(16) h16  g_HNh[(size_t)NNODE * 128];
__device__ __align__(16) float g_HNlast[(size_t)NGRAPH * 128];
__device__ __align__(16) float g_FV[(size_t)NGRAPH * 128];
__device__ __align__(16) h16  g_Wio[256 * 128];
__device__ __align__(16) h16  g_Wg[512 * 384];
__device__ __align__(16) h16  g_Wu[128 * 128];
__device__ __align__(16) h16  g_Wv[128 * 128];
__device__ __align__(16) float g_biasY[256];
__device__ __align__(16) float g_biasG[512];

// ================= helpers =================
__device__ __forceinline__ uint32_t smem_to_u32(const void* p) {
  uint32_t a;
  asm("{ .reg .u64 tmp; cvta.to.shared.u64 tmp, %1; cvt.u32.u64 %0, tmp; }"
      : "=r"(a) : "l"(p));
  return a;
}
#define SWZ(off) ((off) ^ (((off) >> 3) & 0x70))

__device__ __forceinline__ void cp16(uint32_t dst, const void* src) {
  asm volatile("cp.async.cg.shared.global [%0], [%1], 16;" ::"r"(dst), "l"(src));
}
#define CP_COMMIT() asm volatile("cp.async.commit_group;" ::: "memory")
#define CP_WAIT(n) asm volatile("cp.async.wait_group %0;" ::"n"(n) : "memory")

__device__ __forceinline__ void ldsm_x4(uint32_t addr, uint32_t* r) {
  asm volatile("ldmatrix.sync.aligned.m8n8.x4.shared.b16 {%0,%1,%2,%3}, [%4];"
               : "=r"(r[0]), "=r"(r[1]), "=r"(r[2]), "=r"(r[3]) : "r"(addr));
}
__device__ __forceinline__ void mma16816(float* d, const uint32_t* a,
                                         const uint32_t* b) {
  asm volatile(
      "mma.sync.aligned.m16n8k16.row.col.f32.f16.f16.f32 "
      "{%0,%1,%2,%3}, {%4,%5,%6,%7}, {%8,%9}, {%0,%1,%2,%3};"
      : "+f"(d[0]), "+f"(d[1]), "+f"(d[2]), "+f"(d[3])
      : "r"(a[0]), "r"(a[1]), "r"(a[2]), "r"(a[3]), "r"(b[0]), "r"(b[1]));
}

__device__ __forceinline__ float sigf(float x) { return 1.f / (1.f + __expf(-x)); }
__device__ __forceinline__ float tanh_fast(float x) {
  float e2x = __expf(2.f * x);
  return 1.f - 2.f / (e2x + 1.f);
}
__device__ __forceinline__ float h2f(h16 v) { return __half2float(v); }

// ================= adjacency =================
__global__ void k_zero_adj() {
  int i = blockIdx.x * blockDim.x + threadIdx.x;
  int stride = gridDim.x * blockDim.x;
  int4* p = (int4*)g_adj;
  const int n4 = NGRAPH * 1024 / 4;
  int4 z = make_int4(0, 0, 0, 0);
  for (; i < n4; i += stride) p[i] = z;
}
__global__ void k_build_adj(const int* __restrict__ src, const int* __restrict__ dst) {
  int e = blockIdx.x * blockDim.x + threadIdx.x;
  if (e >= NEDGE) return;
  int d = dst[e];
  int s = src[e];
  atomicAdd(&g_adj[((d >> 5) << 10) + ((d & 31) << 5) + (s & 31)], 1);
}

// ================= weight pack + feat convert (merged) =================
__global__ void k_pack(const float* __restrict__ feat,
                       const float* __restrict__ W_in, const float* __restrict__ W_og,
                       const float* __restrict__ W_ih, const float* __restrict__ W_hh,
                       const float* __restrict__ W_u, const float* __restrict__ W_v,
                       const float* __restrict__ b_in, const float* __restrict__ b_og,
                       const float* __restrict__ b_ih, const float* __restrict__ b_hh) {
  int i0 = blockIdx.x * 256 + threadIdx.x;
  int stride = gridDim.x * 256;
  // feat f32 -> fp16 (vectorized)
  {
    const float4* f4 = (const float4*)feat;
    const size_t n4 = (size_t)NNODE * 32;
    for (size_t i = i0; i < n4; i += stride) {
      float4 v = f4[i];
      __half2* dstp = (__half2*)&g_featH[i * 4];
      dstp[0] = __floats2half2_rn(v.x, v.y);
      dstp[1] = __floats2half2_rn(v.z, v.w);
    }
  }
  for (int i = i0; i < 256 * 128; i += stride) {
    int r = i >> 7, c = i & 127;
    float v = (r < 128) ? W_in[r * 128 + c] : W_og[(r - 128) * 128 + c];
    g_Wio[i] = __float2half_rn(v);
  }
  for (int i = i0; i < 512 * 384; i += stride) {
    int r = i / 384, c = i % 384;
    int blk = r >> 7, rr = r & 127;
    float v;
    if (blk == 0)      v = (c < 256) ? W_ih[rr * 256 + c] : W_hh[rr * 128 + (c - 256)];
    else if (blk == 1) v = (c < 256) ? W_ih[(128 + rr) * 256 + c] : W_hh[(128 + rr) * 128 + (c - 256)];
    else if (blk == 2) v = (c < 256) ? W_ih[(256 + rr) * 256 + c] : 0.f;
    else               v = (c < 256) ? 0.f : W_hh[(256 + rr) * 128 + (c - 256)];
    g_Wg[i] = __float2half_rn(v);
  }
  for (int i = i0; i < 128 * 128; i += stride) {
    g_Wu[i] = __float2half_rn(W_u[i]);
    g_Wv[i] = __float2half_rn(W_v[i]);
  }
  for (int i = i0; i < 256; i += stride)
    g_biasY[i] = (i < 128) ? b_in[i] : b_og[i - 128];
  for (int i = i0; i < 512; i += stride) {
    float v;
    if (i < 256)      v = b_ih[i] + b_hh[i];
    else if (i < 384) v = b_ih[i];
    else              v = b_hh[i - 128];
    g_biasG[i] = v;
  }
}

// ================= Y GEMM + fused aggregation (256 thr, 2 CTA/SM) ========
#define YSG 32768   // stage: A 16KB + B 16KB

__global__ void __launch_bounds__(256, 2) k_yagg() {
  extern __shared__ __align__(1024) char smem[];
  const uint32_t sb = smem_to_u32(smem);
  const int tid = threadIdx.x;
  const int lid = tid & 31, wid = tid >> 5;
  const int m0 = blockIdx.x * 128;
  const int nb = blockIdx.y;
  const int g0 = m0 >> 5;
  const int wm0 = (wid & 3) * 32, wn0 = (wid >> 2) * 64;

  const h16* Bh = g_Wio + (size_t)nb * 128 * 128;
  float* adjf = (float*)(smem + 67584);
  float* rdeg = (float*)(smem + 67584 + 16896);

  auto issue = [&](int kc, int s) {
    uint32_t base = sb + s * YSG;
#pragma unroll
    for (int i = 0; i < 4; i++) {
      int u = tid + 256 * i;
      int r = u >> 3, seg = u & 7;
      uint32_t d = SWZ(r * 128 + seg * 16);
      cp16(base + d, g_featH + (size_t)(m0 + r) * 128 + kc + seg * 8);
      cp16(base + 16384 + d, Bh + (size_t)r * 128 + kc + seg * 8);
    }
    CP_COMMIT();
  };

  issue(0, 0);
  issue(64, 1);

  // adjacency + degrees overlap with cp.async latency
#pragma unroll
  for (int i = 0; i < 16; i++) {
    int u = tid + 256 * i;
    int gl = u >> 10, rem = u & 1023;
    adjf[gl * 1056 + (rem >> 5) * 33 + (rem & 31)] =
        (float)g_adj[((size_t)(g0 + gl) << 10) + rem];
  }
  __syncthreads();
  if (tid < 128) {
    int gl = tid >> 5, n = tid & 31;
    float s = 0.f;
#pragma unroll
    for (int k = 0; k < 32; k++)
      s += (nb == 0) ? adjf[gl * 1056 + n * 33 + k]
                     : adjf[gl * 1056 + k * 33 + n];
    rdeg[tid] = 1.f / fmaxf(s, 1.f);
  }

  float acc[2][8][4];
#pragma unroll
  for (int mi = 0; mi < 2; mi++)
#pragma unroll
    for (int ni = 0; ni < 8; ni++)
#pragma unroll
      for (int q = 0; q < 4; q++) acc[mi][ni][q] = 0.f;

  const int j = lid >> 3, rr = lid & 7;
#pragma unroll
  for (int c = 0; c < 2; c++) {
    if (c == 0) CP_WAIT(1); else CP_WAIT(0);
    __syncthreads();
    const uint32_t st = sb + c * YSG;
#pragma unroll
    for (int kk = 0; kk < 4; kk++) {
      uint32_t ah[2][4], bh[8][2];
#pragma unroll
      for (int mi = 0; mi < 2; mi++) {
        int row = wm0 + mi * 16 + (j & 1) * 8 + rr;
        int kb = kk * 32 + (j >> 1) * 16;
        ldsm_x4(st + SWZ(row * 128 + kb), ah[mi]);
      }
#pragma unroll
      for (int p = 0; p < 4; p++) {
        int n = wn0 + p * 16 + (j >> 1) * 8 + rr;
        int kb = kk * 32 + (j & 1) * 16;
        uint32_t t[4];
        ldsm_x4(st + 16384 + SWZ(n * 128 + kb), t);
        bh[2 * p][0] = t[0]; bh[2 * p][1] = t[1];
        bh[2 * p + 1][0] = t[2]; bh[2 * p + 1][1] = t[3];
      }
#pragma unroll
      for (int mi = 0; mi < 2; mi++)
#pragma unroll
        for (int ni = 0; ni < 8; ni++)
          mma16816(acc[mi][ni], ah[mi], bh[ni]);
    }
  }
  __syncthreads();

  // stage C + bias into smem [128][132]
  float* sC = (float*)smem;
  const int gp = lid >> 2, tg = lid & 3;
#pragma unroll
  for (int mi = 0; mi < 2; mi++)
#pragma unroll
    for (int ni = 0; ni < 8; ni++) {
      int r = wm0 + mi * 16 + gp;
      int c = wn0 + ni * 8 + tg * 2;
      float b0 = g_biasY[nb * 128 + c], b1 = g_biasY[nb * 128 + c + 1];
      sC[r * 132 + c] = acc[mi][ni][0] + b0;
      sC[r * 132 + c + 1] = acc[mi][ni][1] + b1;
      sC[(r + 8) * 132 + c] = acc[mi][ni][2] + b0;
      sC[(r + 8) * 132 + c + 1] = acc[mi][ni][3] + b1;
    }
  __syncthreads();

  // per-graph aggregation (256 threads: 4 graphs x 64 cols x 2 col-quads)
  const int gl = tid >> 6, jj = tid & 63;
  float a0[32], a1[32];
#pragma unroll
  for (int n = 0; n < 32; n++) { a0[n] = 0.f; a1[n] = 0.f; }
  for (int k = 0; k < 32; k++) {
    float c0 = sC[(gl * 32 + k) * 132 + jj];
    float c1 = sC[(gl * 32 + k) * 132 + jj + 64];
#pragma unroll
    for (int n = 0; n < 32; n++) {
      float w = (nb == 0) ? adjf[gl * 1056 + n * 33 + k]
                          : adjf[gl * 1056 + k * 33 + n];
      a0[n] += w * c0;
      a1[n] += w * c1;
    }
  }
#pragma unroll
  for (int n = 0; n < 32; n++) {
    float rd = rdeg[gl * 32 + n];
    size_t o = (size_t)(m0 + gl * 32 + n) * 256 + nb * 128 + jj;
    g_AggH[o] = __float2half_rn(a0[n] * rd);
    g_AggH[o + 64] = __float2half_rn(a1[n] * rd);
  }
}

// ================= gates GEMM + fused GRU (resident A, 3-deep B) ==========
// BM=64, 8 warps: warp-pair per gate (warp tile 32x128). 6 K64 chunks.
#define G_A    0           // 6 tiles x 8KB = 48KB resident
#define G_B    49152       // 3 stages x 48KB
#define G_BIAS (49152 + 3 * 49152)
#define SM_GATES (G_BIAS + 2048)

__global__ void __launch_bounds__(256, 1) k_gates() {
  extern __shared__ __align__(1024) char smem[];
  const uint32_t sb = smem_to_u32(smem);
  float* sbias = (float*)(smem + G_BIAS);
  const int tid = threadIdx.x;
  const int lid = tid & 31, wid = tid >> 5;
  const int m0 = blockIdx.x * 64;
  const int gate = wid >> 1;
  const int wm0g = (wid & 1) * 32;

  // resident A: 6 tiles (Agg chunks 0-3, feat chunks 4-5), 12 cp16/thread
#pragma unroll
  for (int i = 0; i < 12; i++) {
    int u = tid + 256 * i;       // 0..3071
    int ch = u >> 9;             // tile
    int rem = u & 511;
    int r = rem >> 3, seg = rem & 7;
    const h16* src = (ch < 4)
        ? g_AggH + (size_t)(m0 + r) * 256 + ch * 64 + seg * 8
        : g_featH + (size_t)(m0 + r) * 128 + (ch - 4) * 64 + seg * 8;
    cp16(sb + G_A + ch * 8192 + SWZ(r * 128 + seg * 16), src);
  }
  CP_COMMIT();

  auto issueB = [&](int ch) {
    uint32_t base = sb + G_B + (ch % 3) * 49152;
#pragma unroll
    for (int slot = 0; slot < 3; slot++) {
      int bg = (slot < 2) ? slot : (ch >= 4 ? 3 : 2);
#pragma unroll
      for (int i = 0; i < 4; i++) {
        int u = tid + 256 * i;
        int r = u >> 3, seg = u & 7;
        cp16(base + slot * 16384 + SWZ(r * 128 + seg * 16),
             g_Wg + (size_t)(bg * 128 + r) * 384 + ch * 64 + seg * 8);
      }
    }
    CP_COMMIT();
  };
  issueB(0);
  issueB(1);
  issueB(2);
  for (int i = tid; i < 512; i += 256) sbias[i] = g_biasG[i];

  float acc[2][16][4];
#pragma unroll
  for (int mi = 0; mi < 2; mi++)
#pragma unroll
    for (int ni = 0; ni < 16; ni++)
#pragma unroll
      for (int q = 0; q < 4; q++) acc[mi][ni][q] = 0.f;

  const int j = lid >> 3, rr = lid & 7;
  for (int ch = 0; ch < 6; ch++) {
    if (ch <= 3) CP_WAIT(2);
    else if (ch == 4) CP_WAIT(1);
    else CP_WAIT(0);
    __syncthreads();
    bool active = (gate == 2) ? (ch < 4) : (gate == 3) ? (ch >= 4) : true;
    if (active) {
      const uint32_t abase = sb + G_A + ch * 8192;
      const uint32_t bbase =
          sb + G_B + (ch % 3) * 49152 + ((gate < 2) ? gate : 2) * 16384;
#pragma unroll
      for (int kk = 0; kk < 4; kk++) {
        uint32_t ah[2][4], bh[16][2];
#pragma unroll
        for (int mi = 0; mi < 2; mi++) {
          int row = wm0g + mi * 16 + (j & 1) * 8 + rr;
          int kb = kk * 32 + (j >> 1) * 16;
          ldsm_x4(abase + SWZ(row * 128 + kb), ah[mi]);
        }
#pragma unroll
        for (int p = 0; p < 8; p++) {
          int n = p * 16 + (j >> 1) * 8 + rr;
          int kb = kk * 32 + (j & 1) * 16;
          uint32_t t[4];
          ldsm_x4(bbase + SWZ(n * 128 + kb), t);
          bh[2 * p][0] = t[0]; bh[2 * p][1] = t[1];
          bh[2 * p + 1][0] = t[2]; bh[2 * p + 1][1] = t[3];
        }
#pragma unroll
        for (int mi = 0; mi < 2; mi++)
#pragma unroll
          for (int ni = 0; ni < 16; ni++)
            mma16816(acc[mi][ni], ah[mi], bh[ni]);
      }
    }
    __syncthreads();
    if (ch + 3 < 6) issueB(ch + 3);
  }

  // ---- extract feat to registers (resident tiles 4,5) ----
  const int frow = tid >> 2;          // 0..63
  const int fc0 = (tid & 3) * 32;     // col base
  float fv[32];
#pragma unroll
  for (int c = 0; c < 32; c++) {
    int col = fc0 + c;
    fv[c] = h2f(*(h16*)(smem + G_A + (4 + (col >> 6)) * 8192 +
                        SWZ(frow * 128 + (col & 63) * 2)));
  }
  __syncthreads();

  // ---- stash gate accumulators to smem sG[4][64][128] f32 ----
  float* sG = (float*)smem;
  const int gp = lid >> 2, tg = lid & 3;
#pragma unroll
  for (int mi = 0; mi < 2; mi++)
#pragma unroll
    for (int ni = 0; ni < 16; ni++) {
      int r = wm0g + mi * 16 + gp;
      int c = ni * 8 + tg * 2;
      sG[gate * 8192 + r * 128 + c] = acc[mi][ni][0];
      sG[gate * 8192 + r * 128 + c + 1] = acc[mi][ni][1];
      sG[gate * 8192 + (r + 8) * 128 + c] = acc[mi][ni][2];
      sG[gate * 8192 + (r + 8) * 128 + c + 1] = acc[mi][ni][3];
    }
  __syncthreads();

  // ---- GRU elementwise -> HNh (+ f32 last-node rows) ----
  const bool lastrow = ((m0 + frow) & 31) == 31;
  const int gidx = (m0 + frow) >> 5;
  __align__(16) h16 oh[32];
#pragma unroll
  for (int c = 0; c < 32; c++) {
    int col = fc0 + c;
    float rs = sG[frow * 128 + col] + sbias[col];
    float zs = sG[8192 + frow * 128 + col] + sbias[128 + col];
    float is = sG[2 * 8192 + frow * 128 + col] + sbias[256 + col];
    float hs = sG[3 * 8192 + frow * 128 + col] + sbias[384 + col];
    float r_ = sigf(rs), z_ = sigf(zs);
    float ng = tanh_fast(is + r_ * hs);
    float hn = (1.f - z_) * ng + z_ * fv[c];
    oh[c] = __float2half_rn(hn);
    if (lastrow) g_HNlast[(size_t)gidx * 128 + col] = hn;
  }
  {
    size_t o = (size_t)(m0 + frow) * 128 + fc0;
    int4* dh = (int4*)&g_HNh[o];
#pragma unroll
    for (int q = 0; q < 4; q++) dh[q] = ((int4*)oh)[q];
  }
}

// ================= FV GEMM (small, 128 thr) =================
#define SG 32768
__global__ void __launch_bounds__(128, 2) k_fv(const float* __restrict__ b_v) {
  extern __shared__ __align__(1024) char smem[];
  const uint32_t sb = smem_to_u32(smem);
  const int tid = threadIdx.x;
  const int lid = tid & 31, wid = tid >> 5;
  const int m0 = blockIdx.x * 128;
  const int wm0 = (wid & 1) * 64, wn0 = (wid >> 1) * 64;

  auto issue = [&](int kc, int s) {
    uint32_t base = sb + s * SG;
#pragma unroll
    for (int i = 0; i < 8; i++) {
      int u = tid + 128 * i;
      int r = u >> 3, seg = u & 7;
      uint32_t d = SWZ(r * 128 + seg * 16);
      cp16(base + d, g_HNh + ((size_t)(m0 + r) * 32 + 31) * 128 + kc + seg * 8);
      cp16(base + 16384 + d, g_Wv + (size_t)r * 128 + kc + seg * 8);
    }
    CP_COMMIT();
  };

  float acc[4][8][4];
#pragma unroll
  for (int mi = 0; mi < 4; mi++)
#pragma unroll
    for (int ni = 0; ni < 8; ni++)
#pragma unroll
      for (int q = 0; q < 4; q++) acc[mi][ni][q] = 0.f;

  issue(0, 0);
  issue(64, 1);
  const int j = lid >> 3, rr = lid & 7;
#pragma unroll
  for (int c = 0; c < 2; c++) {
    if (c == 0) CP_WAIT(1); else CP_WAIT(0);
    __syncthreads();
    const uint32_t st = sb + c * SG;
#pragma unroll
    for (int kk = 0; kk < 4; kk++) {
      uint32_t ah[4][4], bh[8][2];
#pragma unroll
      for (int mi = 0; mi < 4; mi++) {
        int row = wm0 + mi * 16 + (j & 1) * 8 + rr;
        int kb = kk * 32 + (j >> 1) * 16;
        ldsm_x4(st + SWZ(row * 128 + kb), ah[mi]);
      }
#pragma unroll
      for (int p = 0; p < 4; p++) {
        int n = wn0 + p * 16 + (j >> 1) * 8 + rr;
        int kb = kk * 32 + (j & 1) * 16;
        uint32_t t[4];
        ldsm_x4(st + 16384 + SWZ(n * 128 + kb), t);
        bh[2 * p][0] = t[0]; bh[2 * p][1] = t[1];
        bh[2 * p + 1][0] = t[2]; bh[2 * p + 1][1] = t[3];
      }
#pragma unroll
      for (int mi = 0; mi < 4; mi++)
#pragma unroll
        for (int ni = 0; ni < 8; ni++)
          mma16816(acc[mi][ni], ah[mi], bh[ni]);
    }
    __syncthreads();
  }
  const int gp = lid >> 2, tg = lid & 3;
#pragma unroll
  for (int mi = 0; mi < 4; mi++)
#pragma unroll
    for (int ni = 0; ni < 8; ni++) {
      int r0 = m0 + wm0 + mi * 16 + gp;
      int c = wn0 + ni * 8 + tg * 2;
      float b0 = b_v[c], b1 = b_v[c + 1];
      *(float2*)&g_FV[(size_t)r0 * 128 + c] =
          make_float2(acc[mi][ni][0] + b0, acc[mi][ni][1] + b1);
      *(float2*)&g_FV[(size_t)(r0 + 8) * 128 + c] =
          make_float2(acc[mi][ni][2] + b0, acc[mi][ni][3] + b1);
    }
}

// ================= U GEMM + attention + readout (256 thr, 2 CTA/SM) ======
__global__ void __launch_bounds__(256, 2) k_alpha(const float* __restrict__ cnt,
                                                  const float* __restrict__ we,
                                                  float* __restrict__ out) {
  extern __shared__ __align__(1024) char smem[];
  const uint32_t sb = smem_to_u32(smem);
  const int tid = threadIdx.x;
  const int lid = tid & 31, wid = tid >> 5;
  const int m0 = blockIdx.x * 128;
  const int g0 = m0 >> 5;
  const int wm0 = (wid & 3) * 32, wn0 = (wid >> 2) * 64;

  float* sFV = (float*)(smem + 2 * SG);   // [4][128]
  float* swe = sFV + 512;
  float* scnt = swe + 128;
  float* sPart = scnt + 128;              // [2][128]
  float* sAl = sPart + 256;               // [128]

  auto issue = [&](int kc, int s) {
    uint32_t base = sb + s * SG;
#pragma unroll
    for (int i = 0; i < 4; i++) {
      int u = tid + 256 * i;
      int r = u >> 3, seg = u & 7;
      uint32_t d = SWZ(r * 128 + seg * 16);
      cp16(base + d, g_HNh + (size_t)(m0 + r) * 128 + kc + seg * 8);
      cp16(base + 16384 + d, g_Wu + (size_t)r * 128 + kc + seg * 8);
    }
    CP_COMMIT();
  };

  issue(0, 0);
  issue(64, 1);
#pragma unroll
  for (int i = 0; i < 2; i++) {
    int e = tid + 256 * i;
    sFV[e] = g_FV[(size_t)(g0 + (e >> 7)) * 128 + (e & 127)];
  }
  if (tid < 128) { swe[tid] = we[tid]; scnt[tid] = cnt[m0 + tid]; }

  float acc[2][8][4];
#pragma unroll
  for (int mi = 0; mi < 2; mi++)
#pragma unroll
    for (int ni = 0; ni < 8; ni++)
#pragma unroll
      for (int q = 0; q < 4; q++) acc[mi][ni][q] = 0.f;

  const int j = lid >> 3, rr = lid & 7;
#pragma unroll
  for (int c = 0; c < 2; c++) {
    if (c == 0) CP_WAIT(1); else CP_WAIT(0);
    __syncthreads();
    const uint32_t st = sb + c * SG;
#pragma unroll
    for (int kk = 0; kk < 4; kk++) {
      uint32_t ah[2][4], bh[8][2];
#pragma unroll
      for (int mi = 0; mi < 2; mi++) {
        int row = wm0 + mi * 16 + (j & 1) * 8 + rr;
        int kb = kk * 32 + (j >> 1) * 16;
        ldsm_x4(st + SWZ(row * 128 + kb), ah[mi]);
      }
#pragma unroll
      for (int p = 0; p < 4; p++) {
        int n = wn0 + p * 16 + (j >> 1) * 8 + rr;
        int kb = kk * 32 + (j & 1) * 16;
        uint32_t t[4];
        ldsm_x4(st + 16384 + SWZ(n * 128 + kb), t);
        bh[2 * p][0] = t[0]; bh[2 * p][1] = t[1];
        bh[2 * p + 1][0] = t[2]; bh[2 * p + 1][1] = t[3];
      }
#pragma unroll
      for (int mi = 0; mi < 2; mi++)
#pragma unroll
        for (int ni = 0; ni < 8; ni++)
          mma16816(acc[mi][ni], ah[mi], bh[ni]);
    }
  }
  __syncthreads();

  // attention: e[row] = sum_j we[j]*sig(U[row][j] + FV[g][j])
  const int gp = lid >> 2, tg = lid & 3;
#pragma unroll
  for (int mi = 0; mi < 2; mi++) {
    int base = wm0 + mi * 16;
    int gl = base >> 5;
    float p0 = 0.f, p1 = 0.f;
#pragma unroll
    for (int ni = 0; ni < 8; ni++) {
      int jx = wn0 + ni * 8 + tg * 2;
      float fv0 = sFV[gl * 128 + jx], fv1 = sFV[gl * 128 + jx + 1];
      float w0 = swe[jx], w1 = swe[jx + 1];
      p0 += w0 * sigf(acc[mi][ni][0] + fv0) + w1 * sigf(acc[mi][ni][1] + fv1);
      p1 += w0 * sigf(acc[mi][ni][2] + fv0) + w1 * sigf(acc[mi][ni][3] + fv1);
    }
    p0 += __shfl_xor_sync(0xffffffffu, p0, 1);
    p0 += __shfl_xor_sync(0xffffffffu, p0, 2);
    p1 += __shfl_xor_sync(0xffffffffu, p1, 1);
    p1 += __shfl_xor_sync(0xffffffffu, p1, 2);
    if (tg == 0) {
      sPart[(wid >> 2) * 128 + base + gp] = p0;
      sPart[(wid >> 2) * 128 + base + gp + 8] = p1;
    }
  }
  __syncthreads();
  if (tid < 128) sAl[tid] = (sPart[tid] + sPart[128 + tid]) * scnt[tid];
  __syncthreads();

  // readout: hn from HNh tiles resident in both stages; ct_l from f32 rows
#pragma unroll
  for (int v = 0; v < 2; v++) {
    int idx = tid + v * 256;
    int gl = idx >> 7, jx = idx & 127;
    int stg = jx >> 6, cidx = jx & 63;
    float accg = 0.f;
#pragma unroll
    for (int n = 0; n < 32; n++) {
      float hn = h2f(*(h16*)(smem + stg * SG + SWZ((gl * 32 + n) * 128 + cidx * 2)));
      accg += hn * sAl[gl * 32 + n];
    }
    out[(size_t)(g0 + gl) * 256 + jx] = accg;
    out[(size_t)(g0 + gl) * 256 + 128 + jx] =
        g_HNlast[(size_t)(g0 + gl) * 128 + jx];
  }
}

// ================= host =================
extern "C" void kernel_launch(void* const* d_in, const int* in_sizes, int n_in,
                              void* d_out, int out_size) {
  const float* feat = (const float*)d_in[0];
  const float* cnt  = (const float*)d_in[1];
  const float* W_in = (const float*)d_in[2];
  const float* b_in = (const float*)d_in[3];
  const float* W_og = (const float*)d_in[4];
  const float* b_og = (const float*)d_in[5];
  const float* W_ih = (const float*)d_in[6];
  const float* b_ih = (const float*)d_in[7];
  const float* W_hh = (const float*)d_in[8];
  const float* b_hh = (const float*)d_in[9];
  const float* W_u  = (const float*)d_in[10];
  const float* W_v  = (const float*)d_in[11];
  const float* b_v  = (const float*)d_in[12];
  const float* w_e  = (const float*)d_in[13];
  const int*   src  = (const int*)d_in[14];
  const int*   dst  = (const int*)d_in[15];
  float* out = (float*)d_out;

  const int SM_YAGG = 84992;
  const int SM_FV = 2 * SG;
  const int SM_ALPHA = 2 * SG + 4608;
  static bool attr_done = false;
  if (!attr_done) {
    cudaFuncSetAttribute(k_yagg, cudaFuncAttributeMaxDynamicSharedMemorySize, SM_YAGG);
    cudaFuncSetAttribute(k_gates, cudaFuncAttributeMaxDynamicSharedMemorySize, SM_GATES);
    cudaFuncSetAttribute(k_fv, cudaFuncAttributeMaxDynamicSharedMemorySize, SM_FV);
    cudaFuncSetAttribute(k_alpha, cudaFuncAttributeMaxDynamicSharedMemorySize, SM_ALPHA);
    attr_done = true;
  }

  k_zero_adj<<<512, 256>>>();
  k_build_adj<<<NEDGE / 256, 256>>>(src, dst);
  k_pack<<<2048, 256>>>(feat, W_in, W_og, W_ih, W_hh, W_u, W_v,
                        b_in, b_og, b_ih, b_hh);

  k_yagg<<<dim3(NNODE / 128, 2), 256, SM_YAGG>>>();
  k_gates<<<NNODE / 64, 256, SM_GATES>>>();
  k_fv<<<NGRAPH / 128, 128, SM_FV>>>(b_v);
  k_alpha<<<NNODE / 128, 256, SM_ALPHA>>>(cnt, w_e, out);
}

// round 10
// speedup vs baseline: 1.5684x; 1.2204x over previous
#include <cuda_runtime.h>
#include <cuda_fp16.h>
#include <cstdint>

#define NGRAPH 8192
#define NNODE (NGRAPH * 32)
#define NEDGE 524288

typedef __half h16;

// ================= static device scratch =================
__device__ __align__(16) int  g_adj[NGRAPH * 1024];
__device__ __align__(16) h16  g_featH[(size_t)NNODE * 128];
__device__ __align__(16) h16  g_AggH[(size_t)NNODE * 256];
__device__ __align__(16) h16  g_HNh[(size_t)NNODE * 128];
__device__ __align__(16) float g_HNlast[(size_t)NGRAPH * 128];
__device__ __align__(16) float g_FV[(size_t)NGRAPH * 128];
__device__ __align__(16) h16  g_Wio[256 * 128];
__device__ __align__(16) h16  g_Wg[512 * 384];
__device__ __align__(16) h16  g_Wu[128 * 128];
__device__ __align__(16) h16  g_Wv[128 * 128];
__device__ __align__(16) float g_biasY[256];
__device__ __align__(16) float g_biasG[512];

// ================= helpers =================
__device__ __forceinline__ uint32_t smem_to_u32(const void* p) {
  uint32_t a;
  asm("{ .reg .u64 tmp; cvta.to.shared.u64 tmp, %1; cvt.u32.u64 %0, tmp; }"
      : "=r"(a) : "l"(p));
  return a;
}
#define SWZ(off) ((off) ^ (((off) >> 3) & 0x70))

__device__ __forceinline__ void cp16(uint32_t dst, const void* src) {
  asm volatile("cp.async.cg.shared.global [%0], [%1], 16;" ::"r"(dst), "l"(src));
}
#define CP_COMMIT() asm volatile("cp.async.commit_group;" ::: "memory")
#define CP_WAIT(n) asm volatile("cp.async.wait_group %0;" ::"n"(n) : "memory")

__device__ __forceinline__ void ldsm_x4(uint32_t addr, uint32_t* r) {
  asm volatile("ldmatrix.sync.aligned.m8n8.x4.shared.b16 {%0,%1,%2,%3}, [%4];"
               : "=r"(r[0]), "=r"(r[1]), "=r"(r[2]), "=r"(r[3]) : "r"(addr));
}
__device__ __forceinline__ void ldsm_x4_t(uint32_t addr, uint32_t* r) {
  asm volatile("ldmatrix.sync.aligned.m8n8.x4.trans.shared.b16 {%0,%1,%2,%3}, [%4];"
               : "=r"(r[0]), "=r"(r[1]), "=r"(r[2]), "=r"(r[3]) : "r"(addr));
}
__device__ __forceinline__ void mma16816(float* d, const uint32_t* a,
                                         const uint32_t* b) {
  asm volatile(
      "mma.sync.aligned.m16n8k16.row.col.f32.f16.f16.f32 "
      "{%0,%1,%2,%3}, {%4,%5,%6,%7}, {%8,%9}, {%0,%1,%2,%3};"
      : "+f"(d[0]), "+f"(d[1]), "+f"(d[2]), "+f"(d[3])
      : "r"(a[0]), "r"(a[1]), "r"(a[2]), "r"(a[3]), "r"(b[0]), "r"(b[1]));
}

__device__ __forceinline__ float sigf(float x) { return 1.f / (1.f + __expf(-x)); }
__device__ __forceinline__ float tanh_fast(float x) {
  float e2x = __expf(2.f * x);
  return 1.f - 2.f / (e2x + 1.f);
}
__device__ __forceinline__ float h2f(h16 v) { return __half2float(v); }
__device__ __forceinline__ uint32_t pack2h(float a, float b) {
  __half2 h = __floats2half2_rn(a, b);
  return *(uint32_t*)&h;
}

// ================= adjacency =================
__global__ void k_zero_adj() {
  int i = blockIdx.x * blockDim.x + threadIdx.x;
  int stride = gridDim.x * blockDim.x;
  int4* p = (int4*)g_adj;
  const int n4 = NGRAPH * 1024 / 4;
  int4 z = make_int4(0, 0, 0, 0);
  for (; i < n4; i += stride) p[i] = z;
}
__global__ void k_build_adj(const int* __restrict__ src, const int* __restrict__ dst) {
  int e = blockIdx.x * blockDim.x + threadIdx.x;
  if (e >= NEDGE) return;
  int d = dst[e];
  int s = src[e];
  atomicAdd(&g_adj[((d >> 5) << 10) + ((d & 31) << 5) + (s & 31)], 1);
}

// ================= weight pack + feat convert (merged) =================
__global__ void k_pack(const float* __restrict__ feat,
                       const float* __restrict__ W_in, const float* __restrict__ W_og,
                       const float* __restrict__ W_ih, const float* __restrict__ W_hh,
                       const float* __restrict__ W_u, const float* __restrict__ W_v,
                       const float* __restrict__ b_in, const float* __restrict__ b_og,
                       const float* __restrict__ b_ih, const float* __restrict__ b_hh) {
  int i0 = blockIdx.x * 256 + threadIdx.x;
  int stride = gridDim.x * 256;
  {
    const float4* f4 = (const float4*)feat;
    const size_t n4 = (size_t)NNODE * 32;
    for (size_t i = i0; i < n4; i += stride) {
      float4 v = f4[i];
      __half2* dstp = (__half2*)&g_featH[i * 4];
      dstp[0] = __floats2half2_rn(v.x, v.y);
      dstp[1] = __floats2half2_rn(v.z, v.w);
    }
  }
  for (int i = i0; i < 256 * 128; i += stride) {
    int r = i >> 7, c = i & 127;
    float v = (r < 128) ? W_in[r * 128 + c] : W_og[(r - 128) * 128 + c];
    g_Wio[i] = __float2half_rn(v);
  }
  for (int i = i0; i < 512 * 384; i += stride) {
    int r = i / 384, c = i % 384;
    int blk = r >> 7, rr = r & 127;
    float v;
    if (blk == 0)      v = (c < 256) ? W_ih[rr * 256 + c] : W_hh[rr * 128 + (c - 256)];
    else if (blk == 1) v = (c < 256) ? W_ih[(128 + rr) * 256 + c] : W_hh[(128 + rr) * 128 + (c - 256)];
    else if (blk == 2) v = (c < 256) ? W_ih[(256 + rr) * 256 + c] : 0.f;
    else               v = (c < 256) ? 0.f : W_hh[(256 + rr) * 128 + (c - 256)];
    g_Wg[i] = __float2half_rn(v);
  }
  for (int i = i0; i < 128 * 128; i += stride) {
    g_Wu[i] = __float2half_rn(W_u[i]);
    g_Wv[i] = __float2half_rn(W_v[i]);
  }
  for (int i = i0; i < 256; i += stride)
    g_biasY[i] = (i < 128) ? b_in[i] : b_og[i - 128];
  for (int i = i0; i < 512; i += stride) {
    float v;
    if (i < 256)      v = b_ih[i] + b_hh[i];
    else if (i < 384) v = b_ih[i];
    else              v = b_hh[i - 128];
    g_biasG[i] = v;
  }
}

// ================= Y GEMM + TENSORIZED aggregation (256 thr, 2 CTA/SM) ====
#define YSG 32768           // stage: A 16KB + B 16KB
#define Y_ADJ 65536         // fp16 adj tile: 128 rows x 80B = 10240
#define Y_RDEG (65536 + 10240)
#define SM_YAGG (65536 + 10240 + 512)

__global__ void __launch_bounds__(256, 2) k_yagg() {
  extern __shared__ __align__(1024) char smem[];
  const uint32_t sb = smem_to_u32(smem);
  const int tid = threadIdx.x;
  const int lid = tid & 31, wid = tid >> 5;
  const int m0 = blockIdx.x * 128;
  const int nb = blockIdx.y;
  const int g0 = m0 >> 5;
  const int wm0 = (wid & 3) * 32, wn0 = (wid >> 2) * 64;

  const h16* Bh = g_Wio + (size_t)nb * 128 * 128;
  float* rdeg = (float*)(smem + Y_RDEG);

  auto issue = [&](int kc, int s) {
    uint32_t base = sb + s * YSG;
#pragma unroll
    for (int i = 0; i < 4; i++) {
      int u = tid + 256 * i;
      int r = u >> 3, seg = u & 7;
      uint32_t d = SWZ(r * 128 + seg * 16);
      cp16(base + d, g_featH + (size_t)(m0 + r) * 128 + kc + seg * 8);
      cp16(base + 16384 + d, Bh + (size_t)r * 128 + kc + seg * 8);
    }
    CP_COMMIT();
  };

  issue(0, 0);
  issue(64, 1);

  // build fp16 adjacency tile (rows padded to 80B for conflict-free ldsm)
  // nb==0: tile[gl*32+n][k] = adj[gl][n][k];  nb==1: tile[gl*32+k][n]
  const int* adjg = g_adj + ((size_t)g0 << 10);
#pragma unroll
  for (int i = 0; i < 16; i++) {
    int u = tid + 256 * i;
    int gl = u >> 10, rem = u & 1023;
    int n = rem >> 5, k = rem & 31;
    int row, col;
    if (nb == 0) { row = gl * 32 + n; col = k; }
    else { row = gl * 32 + k; col = n; }
    *(h16*)(smem + Y_ADJ + row * 80 + col * 2) =
        __float2half_rn((float)adjg[u]);
  }
  __syncthreads();
  if (tid < 128) {
    float s = 0.f;
#pragma unroll
    for (int k = 0; k < 32; k++)
      s += h2f(*(h16*)(smem + Y_ADJ + tid * 80 + k * 2));
    rdeg[tid] = 1.f / fmaxf(s, 1.f);
  }

  float acc[2][8][4];
#pragma unroll
  for (int mi = 0; mi < 2; mi++)
#pragma unroll
    for (int ni = 0; ni < 8; ni++)
#pragma unroll
      for (int q = 0; q < 4; q++) acc[mi][ni][q] = 0.f;

  const int j = lid >> 3, rr = lid & 7;
#pragma unroll
  for (int c = 0; c < 2; c++) {
    if (c == 0) CP_WAIT(1); else CP_WAIT(0);
    __syncthreads();
    const uint32_t st = sb + c * YSG;
#pragma unroll
    for (int kk = 0; kk < 4; kk++) {
      uint32_t ah[2][4], bh[8][2];
#pragma unroll
      for (int mi = 0; mi < 2; mi++) {
        int row = wm0 + mi * 16 + (j & 1) * 8 + rr;
        int kb = kk * 32 + (j >> 1) * 16;
        ldsm_x4(st + SWZ(row * 128 + kb), ah[mi]);
      }
#pragma unroll
      for (int p = 0; p < 4; p++) {
        int n = wn0 + p * 16 + (j >> 1) * 8 + rr;
        int kb = kk * 32 + (j & 1) * 16;
        uint32_t t[4];
        ldsm_x4(st + 16384 + SWZ(n * 128 + kb), t);
        bh[2 * p][0] = t[0]; bh[2 * p][1] = t[1];
        bh[2 * p + 1][0] = t[2]; bh[2 * p + 1][1] = t[3];
      }
#pragma unroll
      for (int mi = 0; mi < 2; mi++)
#pragma unroll
        for (int ni = 0; ni < 8; ni++)
          mma16816(acc[mi][ni], ah[mi], bh[ni]);
    }
  }
  __syncthreads();

  // store Y + bias as fp16 swizzled tiles at offset 0 (stage area is dead)
  const int gp = lid >> 2, tg = lid & 3;
#pragma unroll
  for (int mi = 0; mi < 2; mi++)
#pragma unroll
    for (int ni = 0; ni < 8; ni++) {
      int r = wm0 + mi * 16 + gp;
      int c = wn0 + ni * 8 + tg * 2;
      float b0 = g_biasY[nb * 128 + c], b1 = g_biasY[nb * 128 + c + 1];
      uint32_t tileo = (c >> 6) * 16384;
      *(uint32_t*)(smem + tileo + SWZ(r * 128 + (c & 63) * 2)) =
          pack2h(acc[mi][ni][0] + b0, acc[mi][ni][1] + b1);
      *(uint32_t*)(smem + tileo + SWZ((r + 8) * 128 + (c & 63) * 2)) =
          pack2h(acc[mi][ni][2] + b0, acc[mi][ni][3] + b1);
    }
  __syncthreads();

  // tensorized aggregation: warp wid handles rows [wid*16, wid*16+16)
  {
    const int arow = wid * 16;
    const int krow0 = (wid >> 1) * 32;   // graph's k-row base in Y tiles
    uint32_t af[2][4];
#pragma unroll
    for (int ks = 0; ks < 2; ks++) {
      uint32_t addr = sb + Y_ADJ + (arow + (j & 1) * 8 + rr) * 80 +
                      (j >> 1) * 16 + ks * 32;
      ldsm_x4(addr, af[ks]);
    }
    float accC[16][4];
#pragma unroll
    for (int nf = 0; nf < 16; nf++)
#pragma unroll
      for (int q = 0; q < 4; q++) accC[nf][q] = 0.f;
#pragma unroll
    for (int p = 0; p < 8; p++) {
#pragma unroll
      for (int ks = 0; ks < 2; ks++) {
        int krow = krow0 + ks * 16 + (j & 1) * 8 + rr;
        int c = p * 16 + (j >> 1) * 8;
        uint32_t t[4];
        ldsm_x4_t(sb + (c >> 6) * 16384 + SWZ(krow * 128 + (c & 63) * 2), t);
        mma16816(accC[2 * p], af[ks], t);
        mma16816(accC[2 * p + 1], af[ks], t + 2);
      }
    }
    // scale by 1/deg and store
#pragma unroll
    for (int nf = 0; nf < 16; nf++) {
      int col = nf * 8 + tg * 2;
      int r0 = arow + gp, r1 = arow + gp + 8;
      float rd0 = rdeg[r0], rd1 = rdeg[r1];
      size_t o0 = (size_t)(m0 + r0) * 256 + nb * 128 + col;
      size_t o1 = (size_t)(m0 + r1) * 256 + nb * 128 + col;
      *(uint32_t*)&g_AggH[o0] = pack2h(accC[nf][0] * rd0, accC[nf][1] * rd0);
      *(uint32_t*)&g_AggH[o1] = pack2h(accC[nf][2] * rd1, accC[nf][3] * rd1);
    }
  }
}

// ================= gates GEMM + fused GRU (resident A, 3-deep B) ==========
#define G_A    0           // 6 tiles x 8KB = 48KB resident
#define G_B    49152       // 3 stages x 48KB
#define G_BIAS (49152 + 3 * 49152)
#define SM_GATES (G_BIAS + 2048)

__global__ void __launch_bounds__(256, 1) k_gates() {
  extern __shared__ __align__(1024) char smem[];
  const uint32_t sb = smem_to_u32(smem);
  float* sbias = (float*)(smem + G_BIAS);
  const int tid = threadIdx.x;
  const int lid = tid & 31, wid = tid >> 5;
  const int m0 = blockIdx.x * 64;
  const int gate = wid >> 1;
  const int wm0g = (wid & 1) * 32;

#pragma unroll
  for (int i = 0; i < 12; i++) {
    int u = tid + 256 * i;
    int ch = u >> 9;
    int rem = u & 511;
    int r = rem >> 3, seg = rem & 7;
    const h16* src = (ch < 4)
        ? g_AggH + (size_t)(m0 + r) * 256 + ch * 64 + seg * 8
        : g_featH + (size_t)(m0 + r) * 128 + (ch - 4) * 64 + seg * 8;
    cp16(sb + G_A + ch * 8192 + SWZ(r * 128 + seg * 16), src);
  }
  CP_COMMIT();

  auto issueB = [&](int ch) {
    uint32_t base = sb + G_B + (ch % 3) * 49152;
#pragma unroll
    for (int slot = 0; slot < 3; slot++) {
      int bg = (slot < 2) ? slot : (ch >= 4 ? 3 : 2);
#pragma unroll
      for (int i = 0; i < 4; i++) {
        int u = tid + 256 * i;
        int r = u >> 3, seg = u & 7;
        cp16(base + slot * 16384 + SWZ(r * 128 + seg * 16),
             g_Wg + (size_t)(bg * 128 + r) * 384 + ch * 64 + seg * 8);
      }
    }
    CP_COMMIT();
  };
  issueB(0);
  issueB(1);
  issueB(2);
  for (int i = tid; i < 512; i += 256) sbias[i] = g_biasG[i];

  float acc[2][16][4];
#pragma unroll
  for (int mi = 0; mi < 2; mi++)
#pragma unroll
    for (int ni = 0; ni < 16; ni++)
#pragma unroll
      for (int q = 0; q < 4; q++) acc[mi][ni][q] = 0.f;

  const int j = lid >> 3, rr = lid & 7;
  for (int ch = 0; ch < 6; ch++) {
    if (ch <= 3) CP_WAIT(2);
    else if (ch == 4) CP_WAIT(1);
    else CP_WAIT(0);
    __syncthreads();
    bool active = (gate == 2) ? (ch < 4) : (gate == 3) ? (ch >= 4) : true;
    if (active) {
      const uint32_t abase = sb + G_A + ch * 8192;
      const uint32_t bbase =
          sb + G_B + (ch % 3) * 49152 + ((gate < 2) ? gate : 2) * 16384;
#pragma unroll
      for (int kk = 0; kk < 4; kk++) {
        uint32_t ah[2][4], bh[16][2];
#pragma unroll
        for (int mi = 0; mi < 2; mi++) {
          int row = wm0g + mi * 16 + (j & 1) * 8 + rr;
          int kb = kk * 32 + (j >> 1) * 16;
          ldsm_x4(abase + SWZ(row * 128 + kb), ah[mi]);
        }
#pragma unroll
        for (int p = 0; p < 8; p++) {
          int n = p * 16 + (j >> 1) * 8 + rr;
          int kb = kk * 32 + (j & 1) * 16;
          uint32_t t[4];
          ldsm_x4(bbase + SWZ(n * 128 + kb), t);
          bh[2 * p][0] = t[0]; bh[2 * p][1] = t[1];
          bh[2 * p + 1][0] = t[2]; bh[2 * p + 1][1] = t[3];
        }
#pragma unroll
        for (int mi = 0; mi < 2; mi++)
#pragma unroll
          for (int ni = 0; ni < 16; ni++)
            mma16816(acc[mi][ni], ah[mi], bh[ni]);
      }
    }
    __syncthreads();
    if (ch + 3 < 6) issueB(ch + 3);
  }

  // ---- extract feat to registers (resident tiles 4,5) ----
  const int frow = tid >> 2;
  const int fc0 = (tid & 3) * 32;
  float fv[32];
#pragma unroll
  for (int c = 0; c < 32; c++) {
    int col = fc0 + c;
    fv[c] = h2f(*(h16*)(smem + G_A + (4 + (col >> 6)) * 8192 +
                        SWZ(frow * 128 + (col & 63) * 2)));
  }
  __syncthreads();

  // ---- stash gate accumulators to smem sG[4][64][128] f32 ----
  float* sG = (float*)smem;
  const int gp = lid >> 2, tg = lid & 3;
#pragma unroll
  for (int mi = 0; mi < 2; mi++)
#pragma unroll
    for (int ni = 0; ni < 16; ni++) {
      int r = wm0g + mi * 16 + gp;
      int c = ni * 8 + tg * 2;
      sG[gate * 8192 + r * 128 + c] = acc[mi][ni][0];
      sG[gate * 8192 + r * 128 + c + 1] = acc[mi][ni][1];
      sG[gate * 8192 + (r + 8) * 128 + c] = acc[mi][ni][2];
      sG[gate * 8192 + (r + 8) * 128 + c + 1] = acc[mi][ni][3];
    }
  __syncthreads();

  // ---- GRU elementwise -> HNh (+ f32 last-node rows) ----
  const bool lastrow = ((m0 + frow) & 31) == 31;
  const int gidx = (m0 + frow) >> 5;
  __align__(16) h16 oh[32];
#pragma unroll
  for (int c = 0; c < 32; c++) {
    int col = fc0 + c;
    float rs = sG[frow * 128 + col] + sbias[col];
    float zs = sG[8192 + frow * 128 + col] + sbias[128 + col];
    float is = sG[2 * 8192 + frow * 128 + col] + sbias[256 + col];
    float hs = sG[3 * 8192 + frow * 128 + col] + sbias[384 + col];
    float r_ = sigf(rs), z_ = sigf(zs);
    float ng = tanh_fast(is + r_ * hs);
    float hn = (1.f - z_) * ng + z_ * fv[c];
    oh[c] = __float2half_rn(hn);
    if (lastrow) g_HNlast[(size_t)gidx * 128 + col] = hn;
  }
  {
    size_t o = (size_t)(m0 + frow) * 128 + fc0;
    int4* dh = (int4*)&g_HNh[o];
#pragma unroll
    for (int q = 0; q < 4; q++) dh[q] = ((int4*)oh)[q];
  }
}

// ================= FV GEMM (small, 128 thr) =================
#define SG 32768
__global__ void __launch_bounds__(128, 2) k_fv(const float* __restrict__ b_v) {
  extern __shared__ __align__(1024) char smem[];
  const uint32_t sb = smem_to_u32(smem);
  const int tid = threadIdx.x;
  const int lid = tid & 31, wid = tid >> 5;
  const int m0 = blockIdx.x * 128;
  const int wm0 = (wid & 1) * 64, wn0 = (wid >> 1) * 64;

  auto issue = [&](int kc, int s) {
    uint32_t base = sb + s * SG;
#pragma unroll
    for (int i = 0; i < 8; i++) {
      int u = tid + 128 * i;
      int r = u >> 3, seg = u & 7;
      uint32_t d = SWZ(r * 128 + seg * 16);
      cp16(base + d, g_HNh + ((size_t)(m0 + r) * 32 + 31) * 128 + kc + seg * 8);
      cp16(base + 16384 + d, g_Wv + (size_t)r * 128 + kc + seg * 8);
    }
    CP_COMMIT();
  };

  float acc[4][8][4];
#pragma unroll
  for (int mi = 0; mi < 4; mi++)
#pragma unroll
    for (int ni = 0; ni < 8; ni++)
#pragma unroll
      for (int q = 0; q < 4; q++) acc[mi][ni][q] = 0.f;

  issue(0, 0);
  issue(64, 1);
  const int j = lid >> 3, rr = lid & 7;
#pragma unroll
  for (int c = 0; c < 2; c++) {
    if (c == 0) CP_WAIT(1); else CP_WAIT(0);
    __syncthreads();
    const uint32_t st = sb + c * SG;
#pragma unroll
    for (int kk = 0; kk < 4; kk++) {
      uint32_t ah[4][4], bh[8][2];
#pragma unroll
      for (int mi = 0; mi < 4; mi++) {
        int row = wm0 + mi * 16 + (j & 1) * 8 + rr;
        int kb = kk * 32 + (j >> 1) * 16;
        ldsm_x4(st + SWZ(row * 128 + kb), ah[mi]);
      }
#pragma unroll
      for (int p = 0; p < 4; p++) {
        int n = wn0 + p * 16 + (j >> 1) * 8 + rr;
        int kb = kk * 32 + (j & 1) * 16;
        uint32_t t[4];
        ldsm_x4(st + 16384 + SWZ(n * 128 + kb), t);
        bh[2 * p][0] = t[0]; bh[2 * p][1] = t[1];
        bh[2 * p + 1][0] = t[2]; bh[2 * p + 1][1] = t[3];
      }
#pragma unroll
      for (int mi = 0; mi < 4; mi++)
#pragma unroll
        for (int ni = 0; ni < 8; ni++)
          mma16816(acc[mi][ni], ah[mi], bh[ni]);
    }
    __syncthreads();
  }
  const int gp = lid >> 2, tg = lid & 3;
#pragma unroll
  for (int mi = 0; mi < 4; mi++)
#pragma unroll
    for (int ni = 0; ni < 8; ni++) {
      int r0 = m0 + wm0 + mi * 16 + gp;
      int c = wn0 + ni * 8 + tg * 2;
      float b0 = b_v[c], b1 = b_v[c + 1];
      *(float2*)&g_FV[(size_t)r0 * 128 + c] =
          make_float2(acc[mi][ni][0] + b0, acc[mi][ni][1] + b1);
      *(float2*)&g_FV[(size_t)(r0 + 8) * 128 + c] =
          make_float2(acc[mi][ni][2] + b0, acc[mi][ni][3] + b1);
    }
}

// ================= U GEMM + attention + readout (256 thr, 2 CTA/SM) ======
__global__ void __launch_bounds__(256, 2) k_alpha(const float* __restrict__ cnt,
                                                  const float* __restrict__ we,
                                                  float* __restrict__ out) {
  extern __shared__ __align__(1024) char smem[];
  const uint32_t sb = smem_to_u32(smem);
  const int tid = threadIdx.x;
  const int lid = tid & 31, wid = tid >> 5;
  const int m0 = blockIdx.x * 128;
  const int g0 = m0 >> 5;
  const int wm0 = (wid & 3) * 32, wn0 = (wid >> 2) * 64;

  float* sFV = (float*)(smem + 2 * SG);   // [4][128]
  float* swe = sFV + 512;
  float* scnt = swe + 128;
  float* sPart = scnt + 128;              // [2][128]
  float* sAl = sPart + 256;               // [128]

  auto issue = [&](int kc, int s) {
    uint32_t base = sb + s * SG;
#pragma unroll
    for (int i = 0; i < 4; i++) {
      int u = tid + 256 * i;
      int r = u >> 3, seg = u & 7;
      uint32_t d = SWZ(r * 128 + seg * 16);
      cp16(base + d, g_HNh + (size_t)(m0 + r) * 128 + kc + seg * 8);
      cp16(base + 16384 + d, g_Wu + (size_t)r * 128 + kc + seg * 8);
    }
    CP_COMMIT();
  };

  issue(0, 0);
  issue(64, 1);
#pragma unroll
  for (int i = 0; i < 2; i++) {
    int e = tid + 256 * i;
    sFV[e] = g_FV[(size_t)(g0 + (e >> 7)) * 128 + (e & 127)];
  }
  if (tid < 128) { swe[tid] = we[tid]; scnt[tid] = cnt[m0 + tid]; }

  float acc[2][8][4];
#pragma unroll
  for (int mi = 0; mi < 2; mi++)
#pragma unroll
    for (int ni = 0; ni < 8; ni++)
#pragma unroll
      for (int q = 0; q < 4; q++) acc[mi][ni][q] = 0.f;

  const int j = lid >> 3, rr = lid & 7;
#pragma unroll
  for (int c = 0; c < 2; c++) {
    if (c == 0) CP_WAIT(1); else CP_WAIT(0);
    __syncthreads();
    const uint32_t st = sb + c * SG;
#pragma unroll
    for (int kk = 0; kk < 4; kk++) {
      uint32_t ah[2][4], bh[8][2];
#pragma unroll
      for (int mi = 0; mi < 2; mi++) {
        int row = wm0 + mi * 16 + (j & 1) * 8 + rr;
        int kb = kk * 32 + (j >> 1) * 16;
        ldsm_x4(st + SWZ(row * 128 + kb), ah[mi]);
      }
#pragma unroll
      for (int p = 0; p < 4; p++) {
        int n = wn0 + p * 16 + (j >> 1) * 8 + rr;
        int kb = kk * 32 + (j & 1) * 16;
        uint32_t t[4];
        ldsm_x4(st + 16384 + SWZ(n * 128 + kb), t);
        bh[2 * p][0] = t[0]; bh[2 * p][1] = t[1];
        bh[2 * p + 1][0] = t[2]; bh[2 * p + 1][1] = t[3];
      }
#pragma unroll
      for (int mi = 0; mi < 2; mi++)
#pragma unroll
        for (int ni = 0; ni < 8; ni++)
          mma16816(acc[mi][ni], ah[mi], bh[ni]);
    }
  }
  __syncthreads();

  const int gp = lid >> 2, tg = lid & 3;
#pragma unroll
  for (int mi = 0; mi < 2; mi++) {
    int base = wm0 + mi * 16;
    int gl = base >> 5;
    float p0 = 0.f, p1 = 0.f;
#pragma unroll
    for (int ni = 0; ni < 8; ni++) {
      int jx = wn0 + ni * 8 + tg * 2;
      float fv0 = sFV[gl * 128 + jx], fv1 = sFV[gl * 128 + jx + 1];
      float w0 = swe[jx], w1 = swe[jx + 1];
      p0 += w0 * sigf(acc[mi][ni][0] + fv0) + w1 * sigf(acc[mi][ni][1] + fv1);
      p1 += w0 * sigf(acc[mi][ni][2] + fv0) + w1 * sigf(acc[mi][ni][3] + fv1);
    }
    p0 += __shfl_xor_sync(0xffffffffu, p0, 1);
    p0 += __shfl_xor_sync(0xffffffffu, p0, 2);
    p1 += __shfl_xor_sync(0xffffffffu, p1, 1);
    p1 += __shfl_xor_sync(0xffffffffu, p1, 2);
    if (tg == 0) {
      sPart[(wid >> 2) * 128 + base + gp] = p0;
      sPart[(wid >> 2) * 128 + base + gp + 8] = p1;
    }
  }
  __syncthreads();
  if (tid < 128) sAl[tid] = (sPart[tid] + sPart[128 + tid]) * scnt[tid];
  __syncthreads();

#pragma unroll
  for (int v = 0; v < 2; v++) {
    int idx = tid + v * 256;
    int gl = idx >> 7, jx = idx & 127;
    int stg = jx >> 6, cidx = jx & 63;
    float accg = 0.f;
#pragma unroll
    for (int n = 0; n < 32; n++) {
      float hn = h2f(*(h16*)(smem + stg * SG + SWZ((gl * 32 + n) * 128 + cidx * 2)));
      accg += hn * sAl[gl * 32 + n];
    }
    out[(size_t)(g0 + gl) * 256 + jx] = accg;
    out[(size_t)(g0 + gl) * 256 + 128 + jx] =
        g_HNlast[(size_t)(g0 + gl) * 128 + jx];
  }
}

// ================= host =================
extern "C" void kernel_launch(void* const* d_in, const int* in_sizes, int n_in,
                              void* d_out, int out_size) {
  const float* feat = (const float*)d_in[0];
  const float* cnt  = (const float*)d_in[1];
  const float* W_in = (const float*)d_in[2];
  const float* b_in = (const float*)d_in[3];
  const float* W_og = (const float*)d_in[4];
  const float* b_og = (const float*)d_in[5];
  const float* W_ih = (const float*)d_in[6];
  const float* b_ih = (const float*)d_in[7];
  const float* W_hh = (const float*)d_in[8];
  const float* b_hh = (const float*)d_in[9];
  const float* W_u  = (const float*)d_in[10];
  const float* W_v  = (const float*)d_in[11];
  const float* b_v  = (const float*)d_in[12];
  const float* w_e  = (const float*)d_in[13];
  const int*   src  = (const int*)d_in[14];
  const int*   dst  = (const int*)d_in[15];
  float* out = (float*)d_out;

  const int SM_FV = 2 * SG;
  const int SM_ALPHA = 2 * SG + 4608;
  static bool attr_done = false;
  if (!attr_done) {
    cudaFuncSetAttribute(k_yagg, cudaFuncAttributeMaxDynamicSharedMemorySize, SM_YAGG);
    cudaFuncSetAttribute(k_gates, cudaFuncAttributeMaxDynamicSharedMemorySize, SM_GATES);
    cudaFuncSetAttribute(k_fv, cudaFuncAttributeMaxDynamicSharedMemorySize, SM_FV);
    cudaFuncSetAttribute(k_alpha, cudaFuncAttributeMaxDynamicSharedMemorySize, SM_ALPHA);
    attr_done = true;
  }

  k_zero_adj<<<512, 256>>>();
  k_build_adj<<<NEDGE / 256, 256>>>(src, dst);
  k_pack<<<2048, 256>>>(feat, W_in, W_og, W_ih, W_hh, W_u, W_v,
                        b_in, b_og, b_ih, b_hh);

  k_yagg<<<dim3(NNODE / 128, 2), 256, SM_YAGG>>>();
  k_gates<<<NNODE / 64, 256, SM_GATES>>>();
  k_fv<<<NGRAPH / 128, 128, SM_FV>>>(b_v);
  k_alpha<<<NNODE / 128, 256, SM_ALPHA>>>(cnt, w_e, out);
}

// round 11
// speedup vs baseline: 2.6977x; 1.7200x over previous
#include <cuda_runtime.h>
#include <cuda_fp16.h>
#include <cstdint>

#define NGRAPH 8192
#define NNODE (NGRAPH * 32)
#define NEDGE 524288

typedef __half h16;

// ================= static device scratch =================
__device__ __align__(16) int  g_adj[NGRAPH * 1024];
__device__ __align__(16) h16  g_featH[(size_t)NNODE * 128];
__device__ __align__(16) h16  g_AggH[(size_t)NNODE * 256];
__device__ __align__(16) h16  g_HNh[(size_t)NNODE * 128];
__device__ __align__(16) float g_HNlast[(size_t)NGRAPH * 128];
__device__ __align__(16) float g_FV[(size_t)NGRAPH * 128];
__device__ __align__(16) h16  g_Wio[256 * 128];
__device__ __align__(16) h16  g_Wg[512 * 384];
__device__ __align__(16) h16  g_Wu[128 * 128];
__device__ __align__(16) h16  g_Wv[128 * 128];
__device__ __align__(16) float g_biasY[256];
__device__ __align__(16) float g_biasG[512];

// ================= helpers =================
__device__ __forceinline__ uint32_t smem_to_u32(const void* p) {
  uint32_t a;
  asm("{ .reg .u64 tmp; cvta.to.shared.u64 tmp, %1; cvt.u32.u64 %0, tmp; }"
      : "=r"(a) : "l"(p));
  return a;
}
#define SWZ(off) ((off) ^ (((off) >> 3) & 0x70))

__device__ __forceinline__ void cp16(uint32_t dst, const void* src) {
  asm volatile("cp.async.cg.shared.global [%0], [%1], 16;" ::"r"(dst), "l"(src));
}
#define CP_COMMIT() asm volatile("cp.async.commit_group;" ::: "memory")
#define CP_WAIT(n) asm volatile("cp.async.wait_group %0;" ::"n"(n) : "memory")

__device__ __forceinline__ void ldsm_x4(uint32_t addr, uint32_t* r) {
  asm volatile("ldmatrix.sync.aligned.m8n8.x4.shared.b16 {%0,%1,%2,%3}, [%4];"
               : "=r"(r[0]), "=r"(r[1]), "=r"(r[2]), "=r"(r[3]) : "r"(addr));
}
__device__ __forceinline__ void ldsm_x4_t(uint32_t addr, uint32_t* r) {
  asm volatile("ldmatrix.sync.aligned.m8n8.x4.trans.shared.b16 {%0,%1,%2,%3}, [%4];"
               : "=r"(r[0]), "=r"(r[1]), "=r"(r[2]), "=r"(r[3]) : "r"(addr));
}
__device__ __forceinline__ void mma16816(float* d, const uint32_t* a,
                                         const uint32_t* b) {
  asm volatile(
      "mma.sync.aligned.m16n8k16.row.col.f32.f16.f16.f32 "
      "{%0,%1,%2,%3}, {%4,%5,%6,%7}, {%8,%9}, {%0,%1,%2,%3};"
      : "+f"(d[0]), "+f"(d[1]), "+f"(d[2]), "+f"(d[3])
      : "r"(a[0]), "r"(a[1]), "r"(a[2]), "r"(a[3]), "r"(b[0]), "r"(b[1]));
}

__device__ __forceinline__ float sigf(float x) { return 1.f / (1.f + __expf(-x)); }
__device__ __forceinline__ float tanh_fast(float x) {
  float e2x = __expf(2.f * x);
  return 1.f - 2.f / (e2x + 1.f);
}
__device__ __forceinline__ float h2f(h16 v) { return __half2float(v); }
__device__ __forceinline__ uint32_t pack2h(float a, float b) {
  __half2 h = __floats2half2_rn(a, b);
  return *(uint32_t*)&h;
}

// ================= adjacency =================
__global__ void k_zero_adj() {
  int i = blockIdx.x * blockDim.x + threadIdx.x;
  int stride = gridDim.x * blockDim.x;
  int4* p = (int4*)g_adj;
  const int n4 = NGRAPH * 1024 / 4;
  int4 z = make_int4(0, 0, 0, 0);
  for (; i < n4; i += stride) p[i] = z;
}
__global__ void k_build_adj(const int* __restrict__ src, const int* __restrict__ dst) {
  int e = blockIdx.x * blockDim.x + threadIdx.x;
  if (e >= NEDGE) return;
  int d = dst[e];
  int s = src[e];
  atomicAdd(&g_adj[((d >> 5) << 10) + ((d & 31) << 5) + (s & 31)], 1);
}

// ================= weight pack + feat convert (merged) =================
__global__ void k_pack(const float* __restrict__ feat,
                       const float* __restrict__ W_in, const float* __restrict__ W_og,
                       const float* __restrict__ W_ih, const float* __restrict__ W_hh,
                       const float* __restrict__ W_u, const float* __restrict__ W_v,
                       const float* __restrict__ b_in, const float* __restrict__ b_og,
                       const float* __restrict__ b_ih, const float* __restrict__ b_hh) {
  int i0 = blockIdx.x * 256 + threadIdx.x;
  int stride = gridDim.x * 256;
  {
    const float4* f4 = (const float4*)feat;
    const size_t n4 = (size_t)NNODE * 32;
    for (size_t i = i0; i < n4; i += stride) {
      float4 v = f4[i];
      __half2* dstp = (__half2*)&g_featH[i * 4];
      dstp[0] = __floats2half2_rn(v.x, v.y);
      dstp[1] = __floats2half2_rn(v.z, v.w);
    }
  }
  for (int i = i0; i < 256 * 128; i += stride) {
    int r = i >> 7, c = i & 127;
    float v = (r < 128) ? W_in[r * 128 + c] : W_og[(r - 128) * 128 + c];
    g_Wio[i] = __float2half_rn(v);
  }
  for (int i = i0; i < 512 * 384; i += stride) {
    int r = i / 384, c = i % 384;
    int blk = r >> 7, rr = r & 127;
    float v;
    if (blk == 0)      v = (c < 256) ? W_ih[rr * 256 + c] : W_hh[rr * 128 + (c - 256)];
    else if (blk == 1) v = (c < 256) ? W_ih[(128 + rr) * 256 + c] : W_hh[(128 + rr) * 128 + (c - 256)];
    else if (blk == 2) v = (c < 256) ? W_ih[(256 + rr) * 256 + c] : 0.f;
    else               v = (c < 256) ? 0.f : W_hh[(256 + rr) * 128 + (c - 256)];
    g_Wg[i] = __float2half_rn(v);
  }
  for (int i = i0; i < 128 * 128; i += stride) {
    g_Wu[i] = __float2half_rn(W_u[i]);
    g_Wv[i] = __float2half_rn(W_v[i]);
  }
  for (int i = i0; i < 256; i += stride)
    g_biasY[i] = (i < 128) ? b_in[i] : b_og[i - 128];
  for (int i = i0; i < 512; i += stride) {
    float v;
    if (i < 256)      v = b_ih[i] + b_hh[i];
    else if (i < 384) v = b_ih[i];
    else              v = b_hh[i - 128];
    g_biasG[i] = v;
  }
}

// ================= Y GEMM + TENSORIZED aggregation (256 thr, 2 CTA/SM) ====
#define YSG 32768           // stage: A 16KB + B 16KB
#define Y_ADJ 65536         // fp16 adj tile: 128 rows x 80B = 10240
#define Y_RDEG (65536 + 10240)
#define SM_YAGG (65536 + 10240 + 512)

__global__ void __launch_bounds__(256, 2) k_yagg() {
  extern __shared__ __align__(1024) char smem[];
  const uint32_t sb = smem_to_u32(smem);
  const int tid = threadIdx.x;
  const int lid = tid & 31, wid = tid >> 5;
  const int m0 = blockIdx.x * 128;
  const int nb = blockIdx.y;
  const int g0 = m0 >> 5;
  const int wm0 = (wid & 3) * 32, wn0 = (wid >> 2) * 64;

  const h16* Bh = g_Wio + (size_t)nb * 128 * 128;
  float* rdeg = (float*)(smem + Y_RDEG);

  auto issue = [&](int kc, int s) {
    uint32_t base = sb + s * YSG;
#pragma unroll
    for (int i = 0; i < 4; i++) {
      int u = tid + 256 * i;
      int r = u >> 3, seg = u & 7;
      uint32_t d = SWZ(r * 128 + seg * 16);
      cp16(base + d, g_featH + (size_t)(m0 + r) * 128 + kc + seg * 8);
      cp16(base + 16384 + d, Bh + (size_t)r * 128 + kc + seg * 8);
    }
    CP_COMMIT();
  };

  issue(0, 0);
  issue(64, 1);

  const int* adjg = g_adj + ((size_t)g0 << 10);
#pragma unroll
  for (int i = 0; i < 16; i++) {
    int u = tid + 256 * i;
    int gl = u >> 10, rem = u & 1023;
    int n = rem >> 5, k = rem & 31;
    int row, col;
    if (nb == 0) { row = gl * 32 + n; col = k; }
    else { row = gl * 32 + k; col = n; }
    *(h16*)(smem + Y_ADJ + row * 80 + col * 2) =
        __float2half_rn((float)adjg[u]);
  }
  __syncthreads();
  if (tid < 128) {
    float s = 0.f;
#pragma unroll
    for (int k = 0; k < 32; k++)
      s += h2f(*(h16*)(smem + Y_ADJ + tid * 80 + k * 2));
    rdeg[tid] = 1.f / fmaxf(s, 1.f);
  }

  float acc[2][8][4];
#pragma unroll
  for (int mi = 0; mi < 2; mi++)
#pragma unroll
    for (int ni = 0; ni < 8; ni++)
#pragma unroll
      for (int q = 0; q < 4; q++) acc[mi][ni][q] = 0.f;

  const int j = lid >> 3, rr = lid & 7;
#pragma unroll
  for (int c = 0; c < 2; c++) {
    if (c == 0) CP_WAIT(1); else CP_WAIT(0);
    __syncthreads();
    const uint32_t st = sb + c * YSG;
#pragma unroll
    for (int kk = 0; kk < 4; kk++) {
      uint32_t ah[2][4], bh[8][2];
#pragma unroll
      for (int mi = 0; mi < 2; mi++) {
        int row = wm0 + mi * 16 + (j & 1) * 8 + rr;
        int kb = kk * 32 + (j >> 1) * 16;
        ldsm_x4(st + SWZ(row * 128 + kb), ah[mi]);
      }
#pragma unroll
      for (int p = 0; p < 4; p++) {
        int n = wn0 + p * 16 + (j >> 1) * 8 + rr;
        int kb = kk * 32 + (j & 1) * 16;
        uint32_t t[4];
        ldsm_x4(st + 16384 + SWZ(n * 128 + kb), t);
        bh[2 * p][0] = t[0]; bh[2 * p][1] = t[1];
        bh[2 * p + 1][0] = t[2]; bh[2 * p + 1][1] = t[3];
      }
#pragma unroll
      for (int mi = 0; mi < 2; mi++)
#pragma unroll
        for (int ni = 0; ni < 8; ni++)
          mma16816(acc[mi][ni], ah[mi], bh[ni]);
    }
  }
  __syncthreads();

  const int gp = lid >> 2, tg = lid & 3;
#pragma unroll
  for (int mi = 0; mi < 2; mi++)
#pragma unroll
    for (int ni = 0; ni < 8; ni++) {
      int r = wm0 + mi * 16 + gp;
      int c = wn0 + ni * 8 + tg * 2;
      float b0 = g_biasY[nb * 128 + c], b1 = g_biasY[nb * 128 + c + 1];
      uint32_t tileo = (c >> 6) * 16384;
      *(uint32_t*)(smem + tileo + SWZ(r * 128 + (c & 63) * 2)) =
          pack2h(acc[mi][ni][0] + b0, acc[mi][ni][1] + b1);
      *(uint32_t*)(smem + tileo + SWZ((r + 8) * 128 + (c & 63) * 2)) =
          pack2h(acc[mi][ni][2] + b0, acc[mi][ni][3] + b1);
    }
  __syncthreads();

  {
    const int arow = wid * 16;
    const int krow0 = (wid >> 1) * 32;
    uint32_t af[2][4];
#pragma unroll
    for (int ks = 0; ks < 2; ks++) {
      uint32_t addr = sb + Y_ADJ + (arow + (j & 1) * 8 + rr) * 80 +
                      (j >> 1) * 16 + ks * 32;
      ldsm_x4(addr, af[ks]);
    }
    float accC[16][4];
#pragma unroll
    for (int nf = 0; nf < 16; nf++)
#pragma unroll
      for (int q = 0; q < 4; q++) accC[nf][q] = 0.f;
#pragma unroll
    for (int p = 0; p < 8; p++) {
#pragma unroll
      for (int ks = 0; ks < 2; ks++) {
        int krow = krow0 + ks * 16 + (j & 1) * 8 + rr;
        int c = p * 16 + (j >> 1) * 8;
        uint32_t t[4];
        ldsm_x4_t(sb + (c >> 6) * 16384 + SWZ(krow * 128 + (c & 63) * 2), t);
        mma16816(accC[2 * p], af[ks], t);
        mma16816(accC[2 * p + 1], af[ks], t + 2);
      }
    }
#pragma unroll
    for (int nf = 0; nf < 16; nf++) {
      int col = nf * 8 + tg * 2;
      int r0 = arow + gp, r1 = arow + gp + 8;
      float rd0 = rdeg[r0], rd1 = rdeg[r1];
      size_t o0 = (size_t)(m0 + r0) * 256 + nb * 128 + col;
      size_t o1 = (size_t)(m0 + r1) * 256 + nb * 128 + col;
      *(uint32_t*)&g_AggH[o0] = pack2h(accC[nf][0] * rd0, accC[nf][1] * rd0);
      *(uint32_t*)&g_AggH[o1] = pack2h(accC[nf][2] * rd1, accC[nf][3] * rd1);
    }
  }
}

// ========== gates GEMM + fused GRU, column-split (2 CTA/SM) ==========
// grid (NNODE/64, 2): CTA = 64 rows x cols [nh*64, nh*64+64) of ALL 4 gates.
#define GA 0            // 2 x 8KB A stages
#define GB 16384        // 2 x 24KB B stages
#define SM_GATES 65536

__global__ void __launch_bounds__(256, 2) k_gates() {
  extern __shared__ __align__(1024) char smem[];
  const uint32_t sb = smem_to_u32(smem);
  const int tid = threadIdx.x;
  const int lid = tid & 31, wid = tid >> 5;
  const int m0 = blockIdx.x * 64;
  const int nh = blockIdx.y;
  const int cs = nh * 64;
  const int gate = wid >> 1;
  const int wm0g = (wid & 1) * 32;

  auto issueA = [&](int ch) {
    uint32_t base = sb + GA + (ch & 1) * 8192;
    const h16* src0;
    int ld, kk;
    if (ch < 4) { src0 = g_AggH; ld = 256; kk = ch * 64; }
    else { src0 = g_featH; ld = 128; kk = (ch - 4) * 64; }
#pragma unroll
    for (int i = 0; i < 2; i++) {
      int u = tid + 256 * i;
      int r = u >> 3, seg = u & 7;
      cp16(base + SWZ(r * 128 + seg * 16),
           src0 + (size_t)(m0 + r) * ld + kk + seg * 8);
    }
  };
  auto issueB = [&](int ch) {
    uint32_t base = sb + GB + (ch & 1) * 24576;
#pragma unroll
    for (int slot = 0; slot < 3; slot++) {
      int bg = (slot < 2) ? slot : (ch >= 4 ? 3 : 2);
#pragma unroll
      for (int i = 0; i < 2; i++) {
        int u = tid + 256 * i;
        int r = u >> 3, seg = u & 7;
        cp16(base + slot * 8192 + SWZ(r * 128 + seg * 16),
             g_Wg + (size_t)(bg * 128 + cs + r) * 384 + ch * 64 + seg * 8);
      }
    }
  };
  issueA(0); issueB(0); CP_COMMIT();
  issueA(1); issueB(1); CP_COMMIT();

  float acc[2][8][4];
#pragma unroll
  for (int mi = 0; mi < 2; mi++)
#pragma unroll
    for (int ni = 0; ni < 8; ni++)
#pragma unroll
      for (int q = 0; q < 4; q++) acc[mi][ni][q] = 0.f;

  const int j = lid >> 3, rr = lid & 7;
  for (int ch = 0; ch < 6; ch++) {
    if (ch < 5) CP_WAIT(1); else CP_WAIT(0);
    __syncthreads();
    bool active = (gate == 2) ? (ch < 4) : (gate == 3) ? (ch >= 4) : true;
    if (active) {
      const uint32_t abase = sb + GA + (ch & 1) * 8192;
      const uint32_t bbase =
          sb + GB + (ch & 1) * 24576 + ((gate < 2) ? gate : 2) * 8192;
#pragma unroll
      for (int kk = 0; kk < 4; kk++) {
        uint32_t ah[2][4], bh[8][2];
#pragma unroll
        for (int mi = 0; mi < 2; mi++) {
          int row = wm0g + mi * 16 + (j & 1) * 8 + rr;
          int kb = kk * 32 + (j >> 1) * 16;
          ldsm_x4(abase + SWZ(row * 128 + kb), ah[mi]);
        }
#pragma unroll
        for (int p = 0; p < 4; p++) {
          int n = p * 16 + (j >> 1) * 8 + rr;
          int kb = kk * 32 + (j & 1) * 16;
          uint32_t t[4];
          ldsm_x4(bbase + SWZ(n * 128 + kb), t);
          bh[2 * p][0] = t[0]; bh[2 * p][1] = t[1];
          bh[2 * p + 1][0] = t[2]; bh[2 * p + 1][1] = t[3];
        }
#pragma unroll
        for (int mi = 0; mi < 2; mi++)
#pragma unroll
          for (int ni = 0; ni < 8; ni++)
            mma16816(acc[mi][ni], ah[mi], bh[ni]);
      }
    }
    __syncthreads();
    if (ch + 2 < 6) { issueA(ch + 2); issueB(ch + 2); CP_COMMIT(); }
  }

  // ---- fused GRU in 2 col-halves (exchange via dead B region) ----
  float* sG = (float*)(smem + GB);   // 4 gates x 64 rows x 32 cols f32 = 32KB
  const int gp = lid >> 2, tg = lid & 3;
  for (int hc = 0; hc < 2; hc++) {
#pragma unroll
    for (int mi = 0; mi < 2; mi++)
#pragma unroll
      for (int nf = 0; nf < 4; nf++) {
        int ni = hc * 4 + nf;
        int c = nf * 8 + tg * 2;
        int r = wm0g + mi * 16 + gp;
        sG[(gate * 64 + r) * 32 + c] = acc[mi][ni][0];
        sG[(gate * 64 + r) * 32 + c + 1] = acc[mi][ni][1];
        sG[(gate * 64 + r + 8) * 32 + c] = acc[mi][ni][2];
        sG[(gate * 64 + r + 8) * 32 + c + 1] = acc[mi][ni][3];
      }
    __syncthreads();
    {
      const int row = tid >> 2, q = tid & 3;
      const int colbase = hc * 32 + q * 8;      // within 64-col slice
      const bool lastrow = (row & 31) == 31;
      __align__(16) h16 oh[8];
#pragma unroll
      for (int c2 = 0; c2 < 4; c2++) {
        uint32_t fh = *(uint32_t*)(smem + GA + nh * 8192 +
                                   SWZ(row * 128 + (colbase + c2 * 2) * 2));
        float2 fvp = __half22float2(*(__half2*)&fh);
#pragma unroll
        for (int c1 = 0; c1 < 2; c1++) {
          int c = c2 * 2 + c1;
          int cc = q * 8 + c;                  // sG col index (0..31)
          int colg = cs + colbase + c;         // global col
          float r_ = sigf(sG[row * 32 + cc] + __ldg(&g_biasG[colg]));
          float z_ = sigf(sG[(64 + row) * 32 + cc] + __ldg(&g_biasG[128 + colg]));
          float is = sG[(128 + row) * 32 + cc] + __ldg(&g_biasG[256 + colg]);
          float hs = sG[(192 + row) * 32 + cc] + __ldg(&g_biasG[384 + colg]);
          float ng = tanh_fast(is + r_ * hs);
          float f = (c1 == 0) ? fvp.x : fvp.y;
          float hn = (1.f - z_) * ng + z_ * f;
          oh[c] = __float2half_rn(hn);
          if (lastrow)
            g_HNlast[(size_t)((m0 + row) >> 5) * 128 + colg] = hn;
        }
      }
      *(int4*)&g_HNh[(size_t)(m0 + row) * 128 + cs + colbase] = *(int4*)oh;
    }
    __syncthreads();
  }
}

// ================= FV GEMM (small, 128 thr) =================
#define SG 32768
__global__ void __launch_bounds__(128, 2) k_fv(const float* __restrict__ b_v) {
  extern __shared__ __align__(1024) char smem[];
  const uint32_t sb = smem_to_u32(smem);
  const int tid = threadIdx.x;
  const int lid = tid & 31, wid = tid >> 5;
  const int m0 = blockIdx.x * 128;
  const int wm0 = (wid & 1) * 64, wn0 = (wid >> 1) * 64;

  auto issue = [&](int kc, int s) {
    uint32_t base = sb + s * SG;
#pragma unroll
    for (int i = 0; i < 8; i++) {
      int u = tid + 128 * i;
      int r = u >> 3, seg = u & 7;
      uint32_t d = SWZ(r * 128 + seg * 16);
      cp16(base + d, g_HNh + ((size_t)(m0 + r) * 32 + 31) * 128 + kc + seg * 8);
      cp16(base + 16384 + d, g_Wv + (size_t)r * 128 + kc + seg * 8);
    }
    CP_COMMIT();
  };

  float acc[4][8][4];
#pragma unroll
  for (int mi = 0; mi < 4; mi++)
#pragma unroll
    for (int ni = 0; ni < 8; ni++)
#pragma unroll
      for (int q = 0; q < 4; q++) acc[mi][ni][q] = 0.f;

  issue(0, 0);
  issue(64, 1);
  const int j = lid >> 3, rr = lid & 7;
#pragma unroll
  for (int c = 0; c < 2; c++) {
    if (c == 0) CP_WAIT(1); else CP_WAIT(0);
    __syncthreads();
    const uint32_t st = sb + c * SG;
#pragma unroll
    for (int kk = 0; kk < 4; kk++) {
      uint32_t ah[4][4], bh[8][2];
#pragma unroll
      for (int mi = 0; mi < 4; mi++) {
        int row = wm0 + mi * 16 + (j & 1) * 8 + rr;
        int kb = kk * 32 + (j >> 1) * 16;
        ldsm_x4(st + SWZ(row * 128 + kb), ah[mi]);
      }
#pragma unroll
      for (int p = 0; p < 4; p++) {
        int n = wn0 + p * 16 + (j >> 1) * 8 + rr;
        int kb = kk * 32 + (j & 1) * 16;
        uint32_t t[4];
        ldsm_x4(st + 16384 + SWZ(n * 128 + kb), t);
        bh[2 * p][0] = t[0]; bh[2 * p][1] = t[1];
        bh[2 * p + 1][0] = t[2]; bh[2 * p + 1][1] = t[3];
      }
#pragma unroll
      for (int mi = 0; mi < 4; mi++)
#pragma unroll
        for (int ni = 0; ni < 8; ni++)
          mma16816(acc[mi][ni], ah[mi], bh[ni]);
    }
    __syncthreads();
  }
  const int gp = lid >> 2, tg = lid & 3;
#pragma unroll
  for (int mi = 0; mi < 4; mi++)
#pragma unroll
    for (int ni = 0; ni < 8; ni++) {
      int r0 = m0 + wm0 + mi * 16 + gp;
      int c = wn0 + ni * 8 + tg * 2;
      float b0 = b_v[c], b1 = b_v[c + 1];
      *(float2*)&g_FV[(size_t)r0 * 128 + c] =
          make_float2(acc[mi][ni][0] + b0, acc[mi][ni][1] + b1);
      *(float2*)&g_FV[(size_t)(r0 + 8) * 128 + c] =
          make_float2(acc[mi][ni][2] + b0, acc[mi][ni][3] + b1);
    }
}

// ================= U GEMM + attention + readout (256 thr, 2 CTA/SM) ======
__global__ void __launch_bounds__(256, 2) k_alpha(const float* __restrict__ cnt,
                                                  const float* __restrict__ we,
                                                  float* __restrict__ out) {
  extern __shared__ __align__(1024) char smem[];
  const uint32_t sb = smem_to_u32(smem);
  const int tid = threadIdx.x;
  const int lid = tid & 31, wid = tid >> 5;
  const int m0 = blockIdx.x * 128;
  const int g0 = m0 >> 5;
  const int wm0 = (wid & 3) * 32, wn0 = (wid >> 2) * 64;

  float* sFV = (float*)(smem + 2 * SG);   // [4][128]
  float* swe = sFV + 512;
  float* scnt = swe + 128;
  float* sPart = scnt + 128;              // [2][128]
  float* sAl = sPart + 256;               // [128]

  auto issue = [&](int kc, int s) {
    uint32_t base = sb + s * SG;
#pragma unroll
    for (int i = 0; i < 4; i++) {
      int u = tid + 256 * i;
      int r = u >> 3, seg = u & 7;
      uint32_t d = SWZ(r * 128 + seg * 16);
      cp16(base + d, g_HNh + (size_t)(m0 + r) * 128 + kc + seg * 8);
      cp16(base + 16384 + d, g_Wu + (size_t)r * 128 + kc + seg * 8);
    }
    CP_COMMIT();
  };

  issue(0, 0);
  issue(64, 1);
#pragma unroll
  for (int i = 0; i < 2; i++) {
    int e = tid + 256 * i;
    sFV[e] = g_FV[(size_t)(g0 + (e >> 7)) * 128 + (e & 127)];
  }
  if (tid < 128) { swe[tid] = we[tid]; scnt[tid] = cnt[m0 + tid]; }

  float acc[2][8][4];
#pragma unroll
  for (int mi = 0; mi < 2; mi++)
#pragma unroll
    for (int ni = 0; ni < 8; ni++)
#pragma unroll
      for (int q = 0; q < 4; q++) acc[mi][ni][q] = 0.f;

  const int j = lid >> 3, rr = lid & 7;
#pragma unroll
  for (int c = 0; c < 2; c++) {
    if (c == 0) CP_WAIT(1); else CP_WAIT(0);
    __syncthreads();
    const uint32_t st = sb + c * SG;
#pragma unroll
    for (int kk = 0; kk < 4; kk++) {
      uint32_t ah[2][4], bh[8][2];
#pragma unroll
      for (int mi = 0; mi < 2; mi++) {
        int row = wm0 + mi * 16 + (j & 1) * 8 + rr;
        int kb = kk * 32 + (j >> 1) * 16;
        ldsm_x4(st + SWZ(row * 128 + kb), ah[mi]);
      }
#pragma unroll
      for (int p = 0; p < 4; p++) {
        int n = wn0 + p * 16 + (j >> 1) * 8 + rr;
        int kb = kk * 32 + (j & 1) * 16;
        uint32_t t[4];
        ldsm_x4(st + 16384 + SWZ(n * 128 + kb), t);
        bh[2 * p][0] = t[0]; bh[2 * p][1] = t[1];
        bh[2 * p + 1][0] = t[2]; bh[2 * p + 1][1] = t[3];
      }
#pragma unroll
      for (int mi = 0; mi < 2; mi++)
#pragma unroll
        for (int ni = 0; ni < 8; ni++)
          mma16816(acc[mi][ni], ah[mi], bh[ni]);
    }
  }
  __syncthreads();

  const int gp = lid >> 2, tg = lid & 3;
#pragma unroll
  for (int mi = 0; mi < 2; mi++) {
    int base = wm0 + mi * 16;
    int gl = base >> 5;
    float p0 = 0.f, p1 = 0.f;
#pragma unroll
    for (int ni = 0; ni < 8; ni++) {
      int jx = wn0 + ni * 8 + tg * 2;
      float fv0 = sFV[gl * 128 + jx], fv1 = sFV[gl * 128 + jx + 1];
      float w0 = swe[jx], w1 = swe[jx + 1];
      p0 += w0 * sigf(acc[mi][ni][0] + fv0) + w1 * sigf(acc[mi][ni][1] + fv1);
      p1 += w0 * sigf(acc[mi][ni][2] + fv0) + w1 * sigf(acc[mi][ni][3] + fv1);
    }
    p0 += __shfl_xor_sync(0xffffffffu, p0, 1);
    p0 += __shfl_xor_sync(0xffffffffu, p0, 2);
    p1 += __shfl_xor_sync(0xffffffffu, p1, 1);
    p1 += __shfl_xor_sync(0xffffffffu, p1, 2);
    if (tg == 0) {
      sPart[(wid >> 2) * 128 + base + gp] = p0;
      sPart[(wid >> 2) * 128 + base + gp + 8] = p1;
    }
  }
  __syncthreads();
  if (tid < 128) sAl[tid] = (sPart[tid] + sPart[128 + tid]) * scnt[tid];
  __syncthreads();

#pragma unroll
  for (int v = 0; v < 2; v++) {
    int idx = tid + v * 256;
    int gl = idx >> 7, jx = idx & 127;
    int stg = jx >> 6, cidx = jx & 63;
    float accg = 0.f;
#pragma unroll
    for (int n = 0; n < 32; n++) {
      float hn = h2f(*(h16*)(smem + stg * SG + SWZ((gl * 32 + n) * 128 + cidx * 2)));
      accg += hn * sAl[gl * 32 + n];
    }
    out[(size_t)(g0 + gl) * 256 + jx] = accg;
    out[(size_t)(g0 + gl) * 256 + 128 + jx] =
        g_HNlast[(size_t)(g0 + gl) * 128 + jx];
  }
}

// ================= host =================
extern "C" void kernel_launch(void* const* d_in, const int* in_sizes, int n_in,
                              void* d_out, int out_size) {
  const float* feat = (const float*)d_in[0];
  const float* cnt  = (const float*)d_in[1];
  const float* W_in = (const float*)d_in[2];
  const float* b_in = (const float*)d_in[3];
  const float* W_og = (const float*)d_in[4];
  const float* b_og = (const float*)d_in[5];
  const float* W_ih = (const float*)d_in[6];
  const float* b_ih = (const float*)d_in[7];
  const float* W_hh = (const float*)d_in[8];
  const float* b_hh = (const float*)d_in[9];
  const float* W_u  = (const float*)d_in[10];
  const float* W_v  = (const float*)d_in[11];
  const float* b_v  = (const float*)d_in[12];
  const float* w_e  = (const float*)d_in[13];
  const int*   src  = (const int*)d_in[14];
  const int*   dst  = (const int*)d_in[15];
  float* out = (float*)d_out;

  const int SM_FV = 2 * SG;
  const int SM_ALPHA = 2 * SG + 4608;
  static bool attr_done = false;
  if (!attr_done) {
    cudaFuncSetAttribute(k_yagg, cudaFuncAttributeMaxDynamicSharedMemorySize, SM_YAGG);
    cudaFuncSetAttribute(k_gates, cudaFuncAttributeMaxDynamicSharedMemorySize, SM_GATES);
    cudaFuncSetAttribute(k_fv, cudaFuncAttributeMaxDynamicSharedMemorySize, SM_FV);
    cudaFuncSetAttribute(k_alpha, cudaFuncAttributeMaxDynamicSharedMemorySize, SM_ALPHA);
    attr_done = true;
  }

  k_zero_adj<<<512, 256>>>();
  k_build_adj<<<NEDGE / 256, 256>>>(src, dst);
  k_pack<<<2048, 256>>>(feat, W_in, W_og, W_ih, W_hh, W_u, W_v,
                        b_in, b_og, b_ih, b_hh);

  k_yagg<<<dim3(NNODE / 128, 2), 256, SM_YAGG>>>();
  k_gates<<<dim3(NNODE / 64, 2), 256, SM_GATES>>>();
  k_fv<<<NGRAPH / 128, 128, SM_FV>>>(b_v);
  k_alpha<<<NNODE / 128, 256, SM_ALPHA>>>(cnt, w_e, out);
}